// round 9
// baseline (speedup 1.0000x reference)
#include <cuda_runtime.h>
#include <cuda_fp16.h>
#include <math.h>

#define NN 65536
#define NE 1048576

// ---------------- scratch (static device globals; no runtime alloc) --------
__device__ int     g_cnt[NN];
__device__ float   g_dis[NN];
__device__ int     g_rowptr[NN + 1];
__device__ int     g_cursor[NN];
__device__ int     g_col[NE];
__device__ float   g_enorm[NE];
__device__ int     g_bsum[64];
__device__ int     g_is64;
__device__ float   g_bufA[(size_t)NN * 256];
__device__ float   g_bufB[(size_t)NN * 256];
__device__ __half  g_bufH[(size_t)NN * 128];   // fp16 gather table (reused per layer)

// ---------------- init: zero degree counters + edge dtype detection --------
__global__ void k_init(const int* __restrict__ ei32) {
    int i = blockIdx.x * blockDim.x + threadIdx.x;
    if (i < NN) g_cnt[i] = 0;
    if (blockIdx.x == 0) {
        __shared__ int cnt;
        if (threadIdx.x == 0) cnt = 0;
        __syncthreads();
        int nz = 0;
        for (int j = threadIdx.x; j < 4096; j += 256)
            if (ei32[2 * j + 1] != 0) nz++;
        atomicAdd(&cnt, nz);
        __syncthreads();
        if (threadIdx.x == 0) g_is64 = (cnt == 0) ? 1 : 0;
    }
}

__device__ __forceinline__ int load_idx(const void* ei, long long pos) {
    if (g_is64) return (int)((const long long*)ei)[pos];
    return ((const int*)ei)[pos];
}

__global__ void k_count(const void* __restrict__ ei) {
    int e = blockIdx.x * blockDim.x + threadIdx.x;
    if (e < NE) {
        int d = load_idx(ei, (long long)NE + e);
        atomicAdd(&g_cnt[d], 1);
    }
}

// block-local exclusive scan of g_cnt -> g_rowptr, block sums -> g_bsum,
// fused dis = rsqrt(deg+1)
__global__ void k_scan_block() {
    __shared__ int sh[1024];
    int i = blockIdx.x * 1024 + threadIdx.x;
    int v = g_cnt[i];
    g_dis[i] = rsqrtf((float)(v + 1));
    sh[threadIdx.x] = v;
    __syncthreads();
    for (int off = 1; off < 1024; off <<= 1) {
        int t = (threadIdx.x >= off) ? sh[threadIdx.x - off] : 0;
        __syncthreads();
        sh[threadIdx.x] += t;
        __syncthreads();
    }
    g_rowptr[i] = sh[threadIdx.x] - v;
    if (threadIdx.x == 1023) g_bsum[blockIdx.x] = sh[1023];
}

// add block offsets (64-partial prefix computed redundantly per block)
__global__ void k_add_offsets() {
    __shared__ int sh[64];
    int i = blockIdx.x * 256 + threadIdx.x;
    if (threadIdx.x < 64) sh[threadIdx.x] = g_bsum[threadIdx.x];
    __syncthreads();
    int b = i >> 10;                 // uniform within block (256 | 1024 ranges)
    int off = 0;
    for (int j = 0; j < b; j++) off += sh[j];
    int r = g_rowptr[i] + off;
    g_rowptr[i] = r;
    g_cursor[i] = r;
    if (i == NN - 1) g_rowptr[NN] = r + g_cnt[i];
}

__global__ void k_fill(const void* __restrict__ ei) {
    int e = blockIdx.x * blockDim.x + threadIdx.x;
    if (e < NE) {
        int s = load_idx(ei, e);
        int d = load_idx(ei, (long long)NE + e);
        int p = atomicAdd(&g_cursor[d], 1);
        g_col[p]   = s;
        g_enorm[p] = g_dis[s] * g_dis[d];
    }
}

// ---------------- fp32 -> fp16 table conversion ----------------------------
__global__ void k_x2h(const float4* __restrict__ x, uint2* __restrict__ xh) {
    int i = blockIdx.x * 256 + threadIdx.x;    // NN*128/4 = 2M float4
    float4 v = x[i];
    __half2 a = __floats2half2_rn(v.x, v.y);
    __half2 b = __floats2half2_rn(v.z, v.w);
    uint2 u;
    u.x = *(unsigned*)&a;
    u.y = *(unsigned*)&b;
    xh[i] = u;
}

// ---------------- aggregation: fp16 gather, fp32 accumulate ----------------
// out[i] = sum_e norm_e * in[src_e] + dis[i]^2 * in[i]; optional fused
// (+bias -> relu -> row softmax) epilogue when SM=true.
template <int D, bool SM>
__global__ void k_agg(const uint2* __restrict__ in, const float* __restrict__ bias,
                      float* __restrict__ out) {
    constexpr int TPN = D / 4;                  // 32 (D=128) or 16 (D=64)
    int node = blockIdx.x * (256 / TPN) + threadIdx.x / TPN;
    int lane = threadIdx.x % TPN;
    int start = g_rowptr[node];
    int end   = g_rowptr[node + 1];
    float4 acc = make_float4(0.f, 0.f, 0.f, 0.f);
    for (int p = start; p < end; ++p) {
        int   s = g_col[p];
        float w = g_enorm[p];
        uint2 u = in[(size_t)s * TPN + lane];
        float2 f0 = __half22float2(*(__half2*)&u.x);
        float2 f1 = __half22float2(*(__half2*)&u.y);
        acc.x += w * f0.x; acc.y += w * f0.y; acc.z += w * f1.x; acc.w += w * f1.y;
    }
    {
        float ds = g_dis[node];
        float w  = ds * ds;
        uint2 u = in[(size_t)node * TPN + lane];
        float2 f0 = __half22float2(*(__half2*)&u.x);
        float2 f1 = __half22float2(*(__half2*)&u.y);
        acc.x += w * f0.x; acc.y += w * f0.y; acc.z += w * f1.x; acc.w += w * f1.y;
    }
    if (!SM) {
        ((float4*)out)[(size_t)node * TPN + lane] = acc;
        return;
    }
    // fused +bias -> relu -> softmax over the D columns (TPN lanes per node)
    int c0 = lane * 4;
    float v[4] = {acc.x + bias[c0], acc.y + bias[c0 + 1],
                  acc.z + bias[c0 + 2], acc.w + bias[c0 + 3]};
    float m = 0.f;
#pragma unroll
    for (int i = 0; i < 4; i++) { v[i] = fmaxf(v[i], 0.f); m = fmaxf(m, v[i]); }
#pragma unroll
    for (int off = TPN / 2; off; off >>= 1)
        m = fmaxf(m, __shfl_xor_sync(0xffffffffu, m, off));
    float s = 0.f;
#pragma unroll
    for (int i = 0; i < 4; i++) { v[i] = expf(v[i] - m); s += v[i]; }
#pragma unroll
    for (int off = TPN / 2; off; off >>= 1)
        s += __shfl_xor_sync(0xffffffffu, s, off);
    float inv = 1.f / s;
    float4 o = make_float4(v[0] * inv, v[1] * inv, v[2] * inv, v[3] * inv);
    ((float4*)out)[(size_t)node * TPN + lane] = o;
}

// ---------------- tf32 tensor-core GEMM (cp.async double-buffered) ---------
// C[M,N] = A[M,K] @ W[K,N] (+bias). BM=128, BN=64, BK=16, 256 threads.
// 8 warps (4M x 2N), warp tile 32x32, mma.m16n8k8 tf32. OutT float or __half.
__device__ __forceinline__ unsigned to_tf32(float x) {
    unsigned u;
    asm("cvt.rna.tf32.f32 %0, %1;" : "=r"(u) : "f"(x));
    return u;
}
__device__ __forceinline__ void cp16(unsigned dst, const void* src) {
    asm volatile("cp.async.cg.shared.global [%0], [%1], 16;" :: "r"(dst), "l"(src));
}

template <typename OutT>
__global__ void k_gemm_tc(const float* __restrict__ A, const float* __restrict__ W,
                          const float* __restrict__ bias, OutT* __restrict__ C,
                          int K, int N) {
    __shared__ float As[2][128 * 20];   // [m][k] fp32, stride 20 (conflict-free)
    __shared__ float Ws[2][16 * 72];    // [k][n] fp32, stride 72 (conflict-free)
    int tid  = threadIdx.x;
    int lane = tid & 31, warp = tid >> 5;
    int warpM = warp & 3, warpN = warp >> 2;
    int qp = lane >> 2, tq = lane & 3;
    int m0 = blockIdx.x * 128, n0 = blockIdx.y * 64;

    unsigned asb = (unsigned)__cvta_generic_to_shared(&As[0][0]);
    unsigned wsb = (unsigned)__cvta_generic_to_shared(&Ws[0][0]);
    int ar = tid >> 2, akq = (tid & 3) * 4;         // A chunk: rows ar, ar+64
    int wr = tid >> 4, wnc = (tid & 15) * 4;        // W chunk

    float acc[2][4][4];
#pragma unroll
    for (int a = 0; a < 2; a++)
#pragma unroll
        for (int b = 0; b < 4; b++)
#pragma unroll
            for (int c = 0; c < 4; c++) acc[a][b][c] = 0.f;

    auto issue = [&](int st, int k0) {
        const float* a0 = &A[(size_t)(m0 + ar) * K + k0 + akq];
        unsigned d0 = asb + (unsigned)(st * 10240 + (ar * 20 + akq) * 4);
        cp16(d0, a0);
        cp16(d0 + 64 * 20 * 4, a0 + (size_t)64 * K);
        const float* w0 = &W[(size_t)(k0 + wr) * N + n0 + wnc];
        unsigned dw = wsb + (unsigned)(st * 4608 + (wr * 72 + wnc) * 4);
        cp16(dw, w0);
    };

    int KT = K >> 4;
    issue(0, 0);
    asm volatile("cp.async.commit_group;");
    for (int kt = 0; kt < KT; kt++) {
        if (kt + 1 < KT) issue((kt + 1) & 1, (kt + 1) * 16);
        asm volatile("cp.async.commit_group;");
        asm volatile("cp.async.wait_group 1;");
        __syncthreads();
        const float* as = &As[kt & 1][0];
        const float* ws = &Ws[kt & 1][0];
#pragma unroll
        for (int kk = 0; kk < 16; kk += 8) {
            unsigned af[2][4], bf[4][2];
#pragma unroll
            for (int mt = 0; mt < 2; mt++) {
                int r = warpM * 32 + mt * 16 + qp;
                af[mt][0] = to_tf32(as[r * 20 + kk + tq]);
                af[mt][1] = to_tf32(as[(r + 8) * 20 + kk + tq]);
                af[mt][2] = to_tf32(as[r * 20 + kk + tq + 4]);
                af[mt][3] = to_tf32(as[(r + 8) * 20 + kk + tq + 4]);
            }
#pragma unroll
            for (int nt = 0; nt < 4; nt++) {
                int c = warpN * 32 + nt * 8 + qp;
                bf[nt][0] = to_tf32(ws[(kk + tq) * 72 + c]);
                bf[nt][1] = to_tf32(ws[(kk + tq + 4) * 72 + c]);
            }
#pragma unroll
            for (int mt = 0; mt < 2; mt++)
#pragma unroll
                for (int nt = 0; nt < 4; nt++) {
                    asm volatile(
                        "mma.sync.aligned.m16n8k8.row.col.f32.tf32.tf32.f32 "
                        "{%0,%1,%2,%3}, {%4,%5,%6,%7}, {%8,%9}, {%0,%1,%2,%3};"
                        : "+f"(acc[mt][nt][0]), "+f"(acc[mt][nt][1]),
                          "+f"(acc[mt][nt][2]), "+f"(acc[mt][nt][3])
                        : "r"(af[mt][0]), "r"(af[mt][1]),
                          "r"(af[mt][2]), "r"(af[mt][3]),
                          "r"(bf[nt][0]), "r"(bf[nt][1]));
                }
        }
        __syncthreads();
    }

#pragma unroll
    for (int mt = 0; mt < 2; mt++) {
#pragma unroll
        for (int nt = 0; nt < 4; nt++) {
            int col = n0 + warpN * 32 + nt * 8 + 2 * tq;
            float b0 = bias ? bias[col] : 0.f;
            float b1 = bias ? bias[col + 1] : 0.f;
            int r = m0 + warpM * 32 + mt * 16 + qp;
            float o00 = acc[mt][nt][0] + b0, o01 = acc[mt][nt][1] + b1;
            float o10 = acc[mt][nt][2] + b0, o11 = acc[mt][nt][3] + b1;
            if (sizeof(OutT) == 4) {
                *(float2*)&((float*)C)[(size_t)r * N + col] = make_float2(o00, o01);
                *(float2*)&((float*)C)[(size_t)(r + 8) * N + col] = make_float2(o10, o11);
            } else {
                __half2 h0 = __floats2half2_rn(o00, o01);
                __half2 h1 = __floats2half2_rn(o10, o11);
                *(__half2*)&((__half*)C)[(size_t)r * N + col] = h0;
                *(__half2*)&((__half*)C)[(size_t)(r + 8) * N + col] = h1;
            }
        }
    }
}

// ---------------- standalone (+bias) -> ReLU -> row softmax (layer 1) ------
template <int D>
__global__ void k_softmax(const float* __restrict__ in, const float* __restrict__ bias,
                          float* __restrict__ out) {
    int row  = blockIdx.x * (blockDim.x >> 5) + (threadIdx.x >> 5);
    int lane = threadIdx.x & 31;
    if (row >= NN) return;
    constexpr int PER = D / 32;
    float v[PER];
    float m = 0.f;
#pragma unroll
    for (int i = 0; i < PER; i++) {
        int c = lane + i * 32;
        float t = in[(size_t)row * D + c];
        if (bias) t += bias[c];
        t = fmaxf(t, 0.f);
        v[i] = t;
        m = fmaxf(m, t);
    }
#pragma unroll
    for (int off = 16; off; off >>= 1) m = fmaxf(m, __shfl_xor_sync(0xffffffffu, m, off));
    float s = 0.f;
#pragma unroll
    for (int i = 0; i < PER; i++) {
        v[i] = expf(v[i] - m);
        s += v[i];
    }
#pragma unroll
    for (int off = 16; off; off >>= 1) s += __shfl_xor_sync(0xffffffffu, s, off);
    float inv = 1.f / s;
#pragma unroll
    for (int i = 0; i < PER; i++)
        out[(size_t)row * D + lane + i * 32] = v[i] * inv;
}

// ---------------- launch ----------------------------------------------------
extern "C" void kernel_launch(void* const* d_in, const int* in_sizes, int n_in,
                              void* d_out, int out_size) {
    const float* x  = (const float*)d_in[0];
    const void*  ei = d_in[1];
    const float* W1 = (const float*)d_in[2];
    const float* b1 = (const float*)d_in[3];
    const float* W2 = (const float*)d_in[4];
    const float* b2 = (const float*)d_in[5];
    const float* W3 = (const float*)d_in[6];
    const float* b3 = (const float*)d_in[7];
    float* out = (float*)d_out;

    float *bufA, *bufB;
    __half* bufH;
    cudaGetSymbolAddress((void**)&bufA, g_bufA);
    cudaGetSymbolAddress((void**)&bufB, g_bufB);
    cudaGetSymbolAddress((void**)&bufH, g_bufH);

    // ---- graph preprocessing (recomputed every launch; deterministic)
    k_init<<<NN / 256, 256>>>((const int*)ei);
    k_count<<<NE / 256, 256>>>(ei);
    k_scan_block<<<64, 1024>>>();
    k_add_offsets<<<NN / 256, 256>>>();
    k_fill<<<NE / 256, 256>>>(ei);

    // ---- layer 1: x->fp16, aggregate(128) -> GEMM(128->256)+b1 -> relu/softmax
    k_x2h<<<NN * 128 / 4 / 256, 256>>>((const float4*)x, (uint2*)bufH);
    k_agg<128, false><<<NN / 8, 256>>>((const uint2*)bufH, nullptr, bufA);
    k_gemm_tc<float><<<dim3(NN / 128, 256 / 64), 256>>>(bufA, W1, b1, bufB, 128, 256);
    k_softmax<256><<<NN / 8, 256>>>(bufB, nullptr, bufA);

    // ---- layer 2: GEMM(256->128)->fp16 table -> aggregate+bias/relu/softmax
    k_gemm_tc<__half><<<dim3(NN / 128, 128 / 64), 256>>>(bufA, W2, nullptr, bufH, 256, 128);
    k_agg<128, true><<<NN / 8, 256>>>((const uint2*)bufH, b2, bufA);

    // ---- layer 3: GEMM(128->64)->fp16 table -> aggregate+bias/relu/softmax -> out
    k_gemm_tc<__half><<<dim3(NN / 128, 64 / 64), 256>>>(bufA, W3, nullptr, bufH, 128, 64);
    k_agg<64, true><<<NN / 16, 256>>>((const uint2*)bufH, b3, out);
}

// round 10
// speedup vs baseline: 1.3861x; 1.3861x over previous
#include <cuda_runtime.h>
#include <cuda_fp16.h>
#include <math.h>

#define NN 65536
#define NE 1048576

// ---------------- scratch (static device globals; no runtime alloc) --------
__device__ int     g_cnt[NN];
__device__ float   g_dis[NN];
__device__ int     g_rowptr[NN + 1];
__device__ int     g_cursor[NN];
__device__ int     g_col[NE];
__device__ float   g_enorm[NE];
__device__ int     g_bsum[64];
__device__ int     g_is64;
__device__ float   g_bufA[(size_t)NN * 256];
__device__ float   g_bufB[(size_t)NN * 256];
__device__ __half  g_bufH[(size_t)NN * 128];   // fp16 gather table (reused per layer)

// ---------------- init: zero degree counters + edge dtype detection --------
// If edge_index is int64, every odd int32 word is a zero high-half (values
// < 65536). If int32, odd words are real indices (P(all 4096 zero) ~ 0).
__global__ void k_init(const int* __restrict__ ei32) {
    int i = blockIdx.x * blockDim.x + threadIdx.x;
    if (i < NN) g_cnt[i] = 0;
    if (blockIdx.x == 0) {
        __shared__ int cnt;
        if (threadIdx.x == 0) cnt = 0;
        __syncthreads();
        int nz = 0;
        for (int j = threadIdx.x; j < 4096; j += 256)
            if (ei32[2 * j + 1] != 0) nz++;
        atomicAdd(&cnt, nz);
        __syncthreads();
        if (threadIdx.x == 0) g_is64 = (cnt == 0) ? 1 : 0;
    }
}

__device__ __forceinline__ int load_idx(const void* ei, long long pos) {
    if (g_is64) return (int)((const long long*)ei)[pos];
    return ((const int*)ei)[pos];
}

__global__ void k_count(const void* __restrict__ ei) {
    int e = blockIdx.x * blockDim.x + threadIdx.x;
    if (e < NE) {
        int d = load_idx(ei, (long long)NE + e);
        atomicAdd(&g_cnt[d], 1);
    }
}

// block-local exclusive scan of g_cnt -> g_rowptr + fused dis = rsqrt(deg+1)
__global__ void k_scan_block() {
    __shared__ int sh[1024];
    int i = blockIdx.x * 1024 + threadIdx.x;
    int v = g_cnt[i];
    g_dis[i] = rsqrtf((float)(v + 1));  // +1 self loop
    sh[threadIdx.x] = v;
    __syncthreads();
    for (int off = 1; off < 1024; off <<= 1) {
        int t = (threadIdx.x >= off) ? sh[threadIdx.x - off] : 0;
        __syncthreads();
        sh[threadIdx.x] += t;
        __syncthreads();
    }
    g_rowptr[i] = sh[threadIdx.x] - v;
    if (threadIdx.x == 1023) g_bsum[blockIdx.x] = sh[1023];
}

__global__ void k_scan_partials() {  // 1 block x 64
    __shared__ int sh[64];
    int v = g_bsum[threadIdx.x];
    sh[threadIdx.x] = v;
    __syncthreads();
    for (int off = 1; off < 64; off <<= 1) {
        int t = (threadIdx.x >= off) ? sh[threadIdx.x - off] : 0;
        __syncthreads();
        sh[threadIdx.x] += t;
        __syncthreads();
    }
    g_bsum[threadIdx.x] = sh[threadIdx.x] - v;
    if (threadIdx.x == 63) g_rowptr[NN] = sh[63];
}

__global__ void k_add_offsets() {
    int i = blockIdx.x * blockDim.x + threadIdx.x;
    if (i < NN) {
        int r = g_rowptr[i] + g_bsum[i >> 10];
        g_rowptr[i] = r;
        g_cursor[i] = r;
    }
}

__global__ void k_fill(const void* __restrict__ ei) {
    int e = blockIdx.x * blockDim.x + threadIdx.x;
    if (e < NE) {
        int s = load_idx(ei, e);
        int d = load_idx(ei, (long long)NE + e);
        int p = atomicAdd(&g_cursor[d], 1);
        g_col[p]   = s;
        g_enorm[p] = g_dis[s] * g_dis[d];
    }
}

// ---------------- fp32 -> fp16 table conversion ----------------------------
__global__ void k_x2h(const float4* __restrict__ x, uint2* __restrict__ xh) {
    int i = blockIdx.x * 256 + threadIdx.x;    // NN*128/4 = 2M float4
    float4 v = x[i];
    __half2 a = __floats2half2_rn(v.x, v.y);
    __half2 b = __floats2half2_rn(v.z, v.w);
    uint2 u;
    u.x = *(unsigned*)&a;
    u.y = *(unsigned*)&b;
    xh[i] = u;
}

// ---------------- aggregation: fp16 gather, fp32 accumulate ----------------
// out[i] = sum_e norm_e * in[src_e] + dis[i]^2 * in[i]; optional fused
// (+bias -> relu -> row softmax) epilogue when SM=true.
template <int D, bool SM>
__global__ void k_agg(const uint2* __restrict__ in, const float* __restrict__ bias,
                      float* __restrict__ out) {
    constexpr int TPN = D / 4;                  // 32 (D=128) or 16 (D=64)
    int node = blockIdx.x * (256 / TPN) + threadIdx.x / TPN;
    int lane = threadIdx.x % TPN;
    int start = g_rowptr[node];
    int end   = g_rowptr[node + 1];
    float4 acc = make_float4(0.f, 0.f, 0.f, 0.f);
    for (int p = start; p < end; ++p) {
        int   s = g_col[p];
        float w = g_enorm[p];
        uint2 u = in[(size_t)s * TPN + lane];
        float2 f0 = __half22float2(*(__half2*)&u.x);
        float2 f1 = __half22float2(*(__half2*)&u.y);
        acc.x += w * f0.x; acc.y += w * f0.y; acc.z += w * f1.x; acc.w += w * f1.y;
    }
    {
        float ds = g_dis[node];
        float w  = ds * ds;
        uint2 u = in[(size_t)node * TPN + lane];
        float2 f0 = __half22float2(*(__half2*)&u.x);
        float2 f1 = __half22float2(*(__half2*)&u.y);
        acc.x += w * f0.x; acc.y += w * f0.y; acc.z += w * f1.x; acc.w += w * f1.y;
    }
    if (!SM) {
        ((float4*)out)[(size_t)node * TPN + lane] = acc;
        return;
    }
    // fused +bias -> relu -> softmax over D columns (TPN lanes per node)
    int c0 = lane * 4;
    float v[4] = {acc.x + bias[c0], acc.y + bias[c0 + 1],
                  acc.z + bias[c0 + 2], acc.w + bias[c0 + 3]};
    float m = 0.f;
#pragma unroll
    for (int i = 0; i < 4; i++) { v[i] = fmaxf(v[i], 0.f); m = fmaxf(m, v[i]); }
#pragma unroll
    for (int off = TPN / 2; off; off >>= 1)
        m = fmaxf(m, __shfl_xor_sync(0xffffffffu, m, off));
    float s = 0.f;
#pragma unroll
    for (int i = 0; i < 4; i++) { v[i] = expf(v[i] - m); s += v[i]; }
#pragma unroll
    for (int off = TPN / 2; off; off >>= 1)
        s += __shfl_xor_sync(0xffffffffu, s, off);
    float inv = 1.f / s;
    float4 o = make_float4(v[0] * inv, v[1] * inv, v[2] * inv, v[3] * inv);
    ((float4*)out)[(size_t)node * TPN + lane] = o;
}

// ---------------- tf32 tensor-core GEMM (round-6 proven body) --------------
// C[M,N] = A[M,K] @ W[K,N] (+bias). BM=128, BN=64, BK=16, 256 threads.
// 8 warps (4M x 2N), warp tile 32x32, mma.m16n8k8 tf32. OutT float or __half.
__device__ __forceinline__ unsigned to_tf32(float x) {
    unsigned u;
    asm("cvt.rna.tf32.f32 %0, %1;" : "=r"(u) : "f"(x));
    return u;
}

template <typename OutT>
__global__ void k_gemm_tc(const float* __restrict__ A, const float* __restrict__ W,
                          const float* __restrict__ bias, OutT* __restrict__ C,
                          int K, int N) {
    __shared__ unsigned As[128 * 20];  // [m][k], stride 20 (conflict-free frags)
    __shared__ unsigned Ws[16 * 72];   // [k][n], stride 72 (conflict-free frags)
    int tid   = threadIdx.x;
    int lane  = tid & 31;
    int warp  = tid >> 5;
    int warpM = warp & 3;
    int warpN = warp >> 2;
    int qp = lane >> 2, tq = lane & 3;
    int m0 = blockIdx.x * 128, n0 = blockIdx.y * 64;

    float acc[2][4][4];
#pragma unroll
    for (int a = 0; a < 2; a++)
#pragma unroll
        for (int b = 0; b < 4; b++)
#pragma unroll
            for (int c = 0; c < 4; c++) acc[a][b][c] = 0.f;

    for (int k0 = 0; k0 < K; k0 += 16) {
#pragma unroll
        for (int i = 0; i < 2; i++) {          // stage A tile (2048 floats)
            int v   = tid + i * 256;
            int row = v >> 2;
            int kq  = (v & 3) * 4;
            float4 a = *(const float4*)&A[(size_t)(m0 + row) * K + k0 + kq];
            unsigned* p = &As[row * 20 + kq];
            p[0] = to_tf32(a.x); p[1] = to_tf32(a.y);
            p[2] = to_tf32(a.z); p[3] = to_tf32(a.w);
        }
        {                                      // stage W tile (1024 floats)
            int krow = tid >> 4;
            int nc   = (tid & 15) * 4;
            float4 w = *(const float4*)&W[(size_t)(k0 + krow) * N + n0 + nc];
            unsigned* p = &Ws[krow * 72 + nc];
            p[0] = to_tf32(w.x); p[1] = to_tf32(w.y);
            p[2] = to_tf32(w.z); p[3] = to_tf32(w.w);
        }
        __syncthreads();
#pragma unroll
        for (int kk = 0; kk < 16; kk += 8) {
            unsigned af[2][4], bf[4][2];
#pragma unroll
            for (int mt = 0; mt < 2; mt++) {
                int r = warpM * 32 + mt * 16 + qp;
                af[mt][0] = As[r * 20 + kk + tq];
                af[mt][1] = As[(r + 8) * 20 + kk + tq];
                af[mt][2] = As[r * 20 + kk + tq + 4];
                af[mt][3] = As[(r + 8) * 20 + kk + tq + 4];
            }
#pragma unroll
            for (int nt = 0; nt < 4; nt++) {
                int c = warpN * 32 + nt * 8 + qp;
                bf[nt][0] = Ws[(kk + tq) * 72 + c];
                bf[nt][1] = Ws[(kk + tq + 4) * 72 + c];
            }
#pragma unroll
            for (int mt = 0; mt < 2; mt++)
#pragma unroll
                for (int nt = 0; nt < 4; nt++) {
                    asm volatile(
                        "mma.sync.aligned.m16n8k8.row.col.f32.tf32.tf32.f32 "
                        "{%0,%1,%2,%3}, {%4,%5,%6,%7}, {%8,%9}, {%0,%1,%2,%3};"
                        : "+f"(acc[mt][nt][0]), "+f"(acc[mt][nt][1]),
                          "+f"(acc[mt][nt][2]), "+f"(acc[mt][nt][3])
                        : "r"(af[mt][0]), "r"(af[mt][1]),
                          "r"(af[mt][2]), "r"(af[mt][3]),
                          "r"(bf[nt][0]), "r"(bf[nt][1]));
                }
        }
        __syncthreads();
    }

#pragma unroll
    for (int mt = 0; mt < 2; mt++) {
#pragma unroll
        for (int nt = 0; nt < 4; nt++) {
            int col = n0 + warpN * 32 + nt * 8 + 2 * tq;
            float b0 = bias ? bias[col] : 0.f;
            float b1 = bias ? bias[col + 1] : 0.f;
            int r = m0 + warpM * 32 + mt * 16 + qp;
            float o00 = acc[mt][nt][0] + b0, o01 = acc[mt][nt][1] + b1;
            float o10 = acc[mt][nt][2] + b0, o11 = acc[mt][nt][3] + b1;
            if (sizeof(OutT) == 4) {
                *(float2*)&((float*)C)[(size_t)r * N + col] = make_float2(o00, o01);
                *(float2*)&((float*)C)[(size_t)(r + 8) * N + col] = make_float2(o10, o11);
            } else {
                __half2 h0 = __floats2half2_rn(o00, o01);
                __half2 h1 = __floats2half2_rn(o10, o11);
                *(__half2*)&((__half*)C)[(size_t)r * N + col] = h0;
                *(__half2*)&((__half*)C)[(size_t)(r + 8) * N + col] = h1;
            }
        }
    }
}

// ---------------- standalone (+bias) -> ReLU -> row softmax (layer 1) ------
template <int D>
__global__ void k_softmax(const float* __restrict__ in, const float* __restrict__ bias,
                          float* __restrict__ out) {
    int row  = blockIdx.x * (blockDim.x >> 5) + (threadIdx.x >> 5);
    int lane = threadIdx.x & 31;
    if (row >= NN) return;
    constexpr int PER = D / 32;
    float v[PER];
    float m = 0.f;
#pragma unroll
    for (int i = 0; i < PER; i++) {
        int c = lane + i * 32;
        float t = in[(size_t)row * D + c];
        if (bias) t += bias[c];
        t = fmaxf(t, 0.f);
        v[i] = t;
        m = fmaxf(m, t);
    }
#pragma unroll
    for (int off = 16; off; off >>= 1) m = fmaxf(m, __shfl_xor_sync(0xffffffffu, m, off));
    float s = 0.f;
#pragma unroll
    for (int i = 0; i < PER; i++) {
        v[i] = expf(v[i] - m);
        s += v[i];
    }
#pragma unroll
    for (int off = 16; off; off >>= 1) s += __shfl_xor_sync(0xffffffffu, s, off);
    float inv = 1.f / s;
#pragma unroll
    for (int i = 0; i < PER; i++)
        out[(size_t)row * D + lane + i * 32] = v[i] * inv;
}

// ---------------- launch ----------------------------------------------------
extern "C" void kernel_launch(void* const* d_in, const int* in_sizes, int n_in,
                              void* d_out, int out_size) {
    const float* x  = (const float*)d_in[0];
    const void*  ei = d_in[1];
    const float* W1 = (const float*)d_in[2];
    const float* b1 = (const float*)d_in[3];
    const float* W2 = (const float*)d_in[4];
    const float* b2 = (const float*)d_in[5];
    const float* W3 = (const float*)d_in[6];
    const float* b3 = (const float*)d_in[7];
    float* out = (float*)d_out;

    float *bufA, *bufB;
    __half* bufH;
    cudaGetSymbolAddress((void**)&bufA, g_bufA);
    cudaGetSymbolAddress((void**)&bufB, g_bufB);
    cudaGetSymbolAddress((void**)&bufH, g_bufH);

    // ---- graph preprocessing (recomputed every launch; deterministic)
    k_init<<<NN / 256, 256>>>((const int*)ei);
    k_count<<<NE / 256, 256>>>(ei);
    k_scan_block<<<64, 1024>>>();
    k_scan_partials<<<1, 64>>>();
    k_add_offsets<<<NN / 256, 256>>>();
    k_fill<<<NE / 256, 256>>>(ei);

    // ---- layer 1: x->fp16, aggregate(128) -> GEMM(128->256)+b1 -> relu/softmax
    k_x2h<<<NN * 128 / 4 / 256, 256>>>((const float4*)x, (uint2*)bufH);
    k_agg<128, false><<<NN / 8, 256>>>((const uint2*)bufH, nullptr, bufA);
    k_gemm_tc<float><<<dim3(NN / 128, 256 / 64), 256>>>(bufA, W1, b1, bufB, 128, 256);
    k_softmax<256><<<NN / 8, 256>>>(bufB, nullptr, bufA);

    // ---- layer 2: GEMM(256->128)->fp16 table -> aggregate+bias/relu/softmax
    k_gemm_tc<__half><<<dim3(NN / 128, 128 / 64), 256>>>(bufA, W2, nullptr, bufH, 256, 128);
    k_agg<128, true><<<NN / 8, 256>>>((const uint2*)bufH, b2, bufA);

    // ---- layer 3: GEMM(128->64)->fp16 table -> aggregate+bias/relu/softmax -> out
    k_gemm_tc<__half><<<dim3(NN / 128, 64 / 64), 256>>>(bufA, W3, nullptr, bufH, 128, 64);
    k_agg<64, true><<<NN / 16, 256>>>((const uint2*)bufH, b3, out);
}

// round 11
// speedup vs baseline: 1.5322x; 1.1054x over previous
#include <cuda_runtime.h>
#include <cuda_fp16.h>
#include <math.h>

#define NN 65536
#define NE 1048576

// ---------------- scratch (static device globals; no runtime alloc) --------
__device__ int     g_cnt[NN];
__device__ float   g_dis[NN];
__device__ int     g_rowptr[NN + 1];
__device__ int     g_cursor[NN];
__device__ int     g_col[NE];
__device__ float   g_enorm[NE];
__device__ int     g_bsum[64];
__device__ int     g_is64;
__device__ float   g_bufA[(size_t)NN * 256];   // reused as __half[NN*512]
__device__ float   g_bufB[(size_t)NN * 256];
__device__ __half  g_bufH[(size_t)NN * 128];   // fp16 gather table
__device__ __half  g_w1h[256 * 128];           // W1^T fp16 [N][K]
__device__ __half  g_w2h[128 * 256];           // W2^T
__device__ __half  g_w3h[64 * 128];            // W3^T

// ---------------- init: zero degree counters + edge dtype detection --------
__global__ void k_init(const int* __restrict__ ei32) {
    int i = blockIdx.x * blockDim.x + threadIdx.x;
    if (i < NN) g_cnt[i] = 0;
    if (blockIdx.x == 0) {
        __shared__ int cnt;
        if (threadIdx.x == 0) cnt = 0;
        __syncthreads();
        int nz = 0;
        for (int j = threadIdx.x; j < 4096; j += 256)
            if (ei32[2 * j + 1] != 0) nz++;
        atomicAdd(&cnt, nz);
        __syncthreads();
        if (threadIdx.x == 0) g_is64 = (cnt == 0) ? 1 : 0;
    }
}

__device__ __forceinline__ int load_idx(const void* ei, long long pos) {
    if (g_is64) return (int)((const long long*)ei)[pos];
    return ((const int*)ei)[pos];
}

__global__ void k_count(const void* __restrict__ ei) {
    int e = blockIdx.x * blockDim.x + threadIdx.x;
    if (e < NE) {
        int d = load_idx(ei, (long long)NE + e);
        atomicAdd(&g_cnt[d], 1);
    }
}

// block-local exclusive scan of g_cnt -> g_rowptr + fused dis = rsqrt(deg+1)
__global__ void k_scan_block() {
    __shared__ int sh[1024];
    int i = blockIdx.x * 1024 + threadIdx.x;
    int v = g_cnt[i];
    g_dis[i] = rsqrtf((float)(v + 1));  // +1 self loop
    sh[threadIdx.x] = v;
    __syncthreads();
    for (int off = 1; off < 1024; off <<= 1) {
        int t = (threadIdx.x >= off) ? sh[threadIdx.x - off] : 0;
        __syncthreads();
        sh[threadIdx.x] += t;
        __syncthreads();
    }
    g_rowptr[i] = sh[threadIdx.x] - v;
    if (threadIdx.x == 1023) g_bsum[blockIdx.x] = sh[1023];
}

// add block offsets (64-partial prefix computed redundantly per block;
// validated in round-9 run)
__global__ void k_add_offsets() {
    __shared__ int sh[64];
    int i = blockIdx.x * 256 + threadIdx.x;
    if (threadIdx.x < 64) sh[threadIdx.x] = g_bsum[threadIdx.x];
    __syncthreads();
    int b = i >> 10;
    int off = 0;
    for (int j = 0; j < b; j++) off += sh[j];
    int r = g_rowptr[i] + off;
    g_rowptr[i] = r;
    g_cursor[i] = r;
    if (i == NN - 1) g_rowptr[NN] = r + g_cnt[i];
}

__global__ void k_fill(const void* __restrict__ ei) {
    int e = blockIdx.x * blockDim.x + threadIdx.x;
    if (e < NE) {
        int s = load_idx(ei, e);
        int d = load_idx(ei, (long long)NE + e);
        int p = atomicAdd(&g_cursor[d], 1);
        g_col[p]   = s;
        g_enorm[p] = g_dis[s] * g_dis[d];
    }
}

// ---------------- weight convert: fp32 [K][N] -> fp16 [N][K] ---------------
__global__ void k_wcvt(const float* __restrict__ src, __half* __restrict__ dst,
                       int K, int N) {
    int i = blockIdx.x * 256 + threadIdx.x;      // over N*K
    int n = i / K, k = i % K;
    dst[i] = __float2half_rn(src[(size_t)k * N + n]);
}

// ---------------- fp32 -> fp16 table conversion ----------------------------
__global__ void k_x2h(const float4* __restrict__ x, uint2* __restrict__ xh) {
    int i = blockIdx.x * 256 + threadIdx.x;
    float4 v = x[i];
    __half2 a = __floats2half2_rn(v.x, v.y);
    __half2 b = __floats2half2_rn(v.z, v.w);
    uint2 u;
    u.x = *(unsigned*)&a;
    u.y = *(unsigned*)&b;
    xh[i] = u;
}

// ---------------- aggregation: fp16 gather, fp32 accumulate ----------------
// out[i] = sum_e norm_e * in[src_e] + dis[i]^2 * in[i]; optional fused
// (+bias -> relu -> row softmax) epilogue. OutT: __half or float.
template <int D, bool SM, typename OutT>
__global__ void k_agg(const uint2* __restrict__ in, const float* __restrict__ bias,
                      OutT* __restrict__ out) {
    constexpr int TPN = D / 4;                  // 32 (D=128) or 16 (D=64)
    int node = blockIdx.x * (256 / TPN) + threadIdx.x / TPN;
    int lane = threadIdx.x % TPN;
    int start = g_rowptr[node];
    int end   = g_rowptr[node + 1];
    float4 acc = make_float4(0.f, 0.f, 0.f, 0.f);
    for (int p = start; p < end; ++p) {
        int   s = g_col[p];
        float w = g_enorm[p];
        uint2 u = in[(size_t)s * TPN + lane];
        float2 f0 = __half22float2(*(__half2*)&u.x);
        float2 f1 = __half22float2(*(__half2*)&u.y);
        acc.x += w * f0.x; acc.y += w * f0.y; acc.z += w * f1.x; acc.w += w * f1.y;
    }
    {
        float ds = g_dis[node];
        float w  = ds * ds;
        uint2 u = in[(size_t)node * TPN + lane];
        float2 f0 = __half22float2(*(__half2*)&u.x);
        float2 f1 = __half22float2(*(__half2*)&u.y);
        acc.x += w * f0.x; acc.y += w * f0.y; acc.z += w * f1.x; acc.w += w * f1.y;
    }
    float v[4] = {acc.x, acc.y, acc.z, acc.w};
    if (SM) {
        int c0 = lane * 4;
        float m = 0.f;
#pragma unroll
        for (int i = 0; i < 4; i++) {
            v[i] = fmaxf(v[i] + bias[c0 + i], 0.f);
            m = fmaxf(m, v[i]);
        }
#pragma unroll
        for (int off = TPN / 2; off; off >>= 1)
            m = fmaxf(m, __shfl_xor_sync(0xffffffffu, m, off));
        float s = 0.f;
#pragma unroll
        for (int i = 0; i < 4; i++) { v[i] = expf(v[i] - m); s += v[i]; }
#pragma unroll
        for (int off = TPN / 2; off; off >>= 1)
            s += __shfl_xor_sync(0xffffffffu, s, off);
        float inv = 1.f / s;
#pragma unroll
        for (int i = 0; i < 4; i++) v[i] *= inv;
    }
    if (sizeof(OutT) == 4) {
        ((float4*)out)[(size_t)node * TPN + lane] = make_float4(v[0], v[1], v[2], v[3]);
    } else {
        __half2 h0 = __floats2half2_rn(v[0], v[1]);
        __half2 h1 = __floats2half2_rn(v[2], v[3]);
        uint2 u;
        u.x = *(unsigned*)&h0;
        u.y = *(unsigned*)&h1;
        ((uint2*)out)[(size_t)node * TPN + lane] = u;
    }
}

// ---------------- fp16 tensor-core GEMM (round-6 proven skeleton) ----------
// C[M,N] = A[M,K] @ Wt[N,K]^T (+bias). A fp16 row-major, Wt fp16 [N][K].
// BM=128, BN=64, BK=16. 8 warps (4M x 2N), warp tile 32x32, mma.m16n8k16.
// smem stride 12 half2 per row: qp*12+{tq,tq+4} covers all 32 banks.
__global__ void k_gemm_h(const __half* __restrict__ A, const __half* __restrict__ Wt,
                         const float* __restrict__ bias, __half* __restrict__ C,
                         int K, int N) {
    __shared__ __half2 As2[128 * 12];   // [m][k/2], stride 12
    __shared__ __half2 Ws2[64 * 12];    // [n][k/2], stride 12
    int tid   = threadIdx.x;
    int lane  = tid & 31;
    int warp  = tid >> 5;
    int warpM = warp & 3;
    int warpN = warp >> 2;
    int qp = lane >> 2, tq = lane & 3;
    int m0 = blockIdx.x * 128, n0 = blockIdx.y * 64;

    int arow = tid >> 1, ach = (tid & 1) * 8;       // A: 128 rows x 2 chunks of 8 halves
    int wrow = tid >> 2, wch = (tid & 3) * 4;       // W: 64 rows x 4 chunks of 4 halves

    float acc[2][4][4];
#pragma unroll
    for (int a = 0; a < 2; a++)
#pragma unroll
        for (int b = 0; b < 4; b++)
#pragma unroll
            for (int c = 0; c < 4; c++) acc[a][b][c] = 0.f;

    for (int k0 = 0; k0 < K; k0 += 16) {
        {   // stage A tile: one uint4 (8 halves) per thread
            uint4 a = *(const uint4*)&A[(size_t)(m0 + arow) * K + k0 + ach];
            *(uint4*)&As2[arow * 12 + ach / 2] = a;
        }
        {   // stage W tile: one uint2 (4 halves) per thread
            uint2 w = *(const uint2*)&Wt[(size_t)(n0 + wrow) * K + k0 + wch];
            *(uint2*)&Ws2[wrow * 12 + wch / 2] = w;
        }
        __syncthreads();
        unsigned af[2][4], bf[4][2];
#pragma unroll
        for (int mt = 0; mt < 2; mt++) {
            int r = warpM * 32 + mt * 16 + qp;
            af[mt][0] = *(unsigned*)&As2[r * 12 + tq];
            af[mt][1] = *(unsigned*)&As2[(r + 8) * 12 + tq];
            af[mt][2] = *(unsigned*)&As2[r * 12 + tq + 4];
            af[mt][3] = *(unsigned*)&As2[(r + 8) * 12 + tq + 4];
        }
#pragma unroll
        for (int nt = 0; nt < 4; nt++) {
            int c = warpN * 32 + nt * 8 + qp;
            bf[nt][0] = *(unsigned*)&Ws2[c * 12 + tq];
            bf[nt][1] = *(unsigned*)&Ws2[c * 12 + tq + 4];
        }
#pragma unroll
        for (int mt = 0; mt < 2; mt++)
#pragma unroll
            for (int nt = 0; nt < 4; nt++) {
                asm volatile(
                    "mma.sync.aligned.m16n8k16.row.col.f32.f16.f16.f32 "
                    "{%0,%1,%2,%3}, {%4,%5,%6,%7}, {%8,%9}, {%0,%1,%2,%3};"
                    : "+f"(acc[mt][nt][0]), "+f"(acc[mt][nt][1]),
                      "+f"(acc[mt][nt][2]), "+f"(acc[mt][nt][3])
                    : "r"(af[mt][0]), "r"(af[mt][1]),
                      "r"(af[mt][2]), "r"(af[mt][3]),
                      "r"(bf[nt][0]), "r"(bf[nt][1]));
            }
        __syncthreads();
    }

#pragma unroll
    for (int mt = 0; mt < 2; mt++) {
#pragma unroll
        for (int nt = 0; nt < 4; nt++) {
            int col = n0 + warpN * 32 + nt * 8 + 2 * tq;
            float b0 = bias ? bias[col] : 0.f;
            float b1 = bias ? bias[col + 1] : 0.f;
            int r = m0 + warpM * 32 + mt * 16 + qp;
            __half2 h0 = __floats2half2_rn(acc[mt][nt][0] + b0, acc[mt][nt][1] + b1);
            __half2 h1 = __floats2half2_rn(acc[mt][nt][2] + b0, acc[mt][nt][3] + b1);
            *(__half2*)&C[(size_t)r * N + col] = h0;
            *(__half2*)&C[(size_t)(r + 8) * N + col] = h1;
        }
    }
}

// ---------------- fp16 in/out ReLU -> row softmax (layer 1) ----------------
template <int D>
__global__ void k_softmax_h(const __half* __restrict__ in, __half* __restrict__ out) {
    int row  = blockIdx.x * (blockDim.x >> 5) + (threadIdx.x >> 5);
    int lane = threadIdx.x & 31;
    constexpr int PER = D / 32;
    float v[PER];
    float m = 0.f;
#pragma unroll
    for (int i = 0; i < PER; i++) {
        float t = __half2float(in[(size_t)row * D + lane + i * 32]);
        t = fmaxf(t, 0.f);
        v[i] = t;
        m = fmaxf(m, t);
    }
#pragma unroll
    for (int off = 16; off; off >>= 1) m = fmaxf(m, __shfl_xor_sync(0xffffffffu, m, off));
    float s = 0.f;
#pragma unroll
    for (int i = 0; i < PER; i++) {
        v[i] = expf(v[i] - m);
        s += v[i];
    }
#pragma unroll
    for (int off = 16; off; off >>= 1) s += __shfl_xor_sync(0xffffffffu, s, off);
    float inv = 1.f / s;
#pragma unroll
    for (int i = 0; i < PER; i++)
        out[(size_t)row * D + lane + i * 32] = __float2half_rn(v[i] * inv);
}

// ---------------- launch ----------------------------------------------------
extern "C" void kernel_launch(void* const* d_in, const int* in_sizes, int n_in,
                              void* d_out, int out_size) {
    const float* x  = (const float*)d_in[0];
    const void*  ei = d_in[1];
    const float* W1 = (const float*)d_in[2];
    const float* b1 = (const float*)d_in[3];
    const float* W2 = (const float*)d_in[4];
    const float* b2 = (const float*)d_in[5];
    const float* W3 = (const float*)d_in[6];
    const float* b3 = (const float*)d_in[7];
    float* out = (float*)d_out;

    __half *bufAh, *bufBh, *bufH, *w1h, *w2h, *w3h;
    cudaGetSymbolAddress((void**)&bufAh, g_bufA);
    cudaGetSymbolAddress((void**)&bufBh, g_bufB);
    cudaGetSymbolAddress((void**)&bufH, g_bufH);
    cudaGetSymbolAddress((void**)&w1h, g_w1h);
    cudaGetSymbolAddress((void**)&w2h, g_w2h);
    cudaGetSymbolAddress((void**)&w3h, g_w3h);

    // ---- graph preprocessing + weight conversion (every launch; deterministic)
    k_init<<<NN / 256, 256>>>((const int*)ei);
    k_count<<<NE / 256, 256>>>(ei);
    k_scan_block<<<64, 1024>>>();
    k_add_offsets<<<NN / 256, 256>>>();
    k_fill<<<NE / 256, 256>>>(ei);
    k_wcvt<<<256 * 128 / 256, 256>>>(W1, w1h, 128, 256);
    k_wcvt<<<128 * 256 / 256, 256>>>(W2, w2h, 256, 128);
    k_wcvt<<<64 * 128 / 256, 256>>>(W3, w3h, 128, 64);

    // ---- layer 1: x->fp16 table, aggregate(128) -> GEMM(128->256)+b1 -> softmax
    k_x2h<<<NN * 128 / 4 / 256, 256>>>((const float4*)x, (uint2*)bufH);
    k_agg<128, false, __half><<<NN / 8, 256>>>((const uint2*)bufH, nullptr, bufAh);
    k_gemm_h<<<dim3(NN / 128, 256 / 64), 256>>>(bufAh, w1h, b1, bufBh, 128, 256);
    k_softmax_h<256><<<NN / 8, 256>>>(bufBh, bufAh);

    // ---- layer 2: GEMM(256->128)->fp16 table -> aggregate+bias/relu/softmax
    k_gemm_h<<<dim3(NN / 128, 128 / 64), 256>>>(bufAh, w2h, nullptr, bufH, 256, 128);
    k_agg<128, true, __half><<<NN / 8, 256>>>((const uint2*)bufH, b2, bufBh);

    // ---- layer 3: GEMM(128->64)->fp16 table -> aggregate+bias/relu/softmax -> out
    k_gemm_h<<<dim3(NN / 128, 64 / 64), 256>>>(bufBh, w3h, nullptr, bufH, 128, 64);
    k_agg<64, true, float><<<NN / 16, 256>>>((const uint2*)bufH, b3, out);
}

// round 12
// speedup vs baseline: 1.6675x; 1.0884x over previous
#include <cuda_runtime.h>
#include <cuda_fp16.h>
#include <math.h>

#define NN 65536
#define NE 1048576

// ---------------- scratch (static device globals; no runtime alloc) --------
__device__ int     g_cnt[NN];
__device__ float   g_dis[NN];
__device__ int     g_rowptr[NN + 1];
__device__ int     g_cursor[NN];
__device__ int     g_col[NE];
__device__ float   g_enorm[NE];
__device__ int     g_bsum[64];
__device__ int     g_is64;
__device__ float   g_bufA[(size_t)NN * 256];   // reused as __half[NN*512]
__device__ float   g_bufB[(size_t)NN * 256];
__device__ __half  g_bufH[(size_t)NN * 128];   // fp16 gather table
__device__ __half  g_w1h[256 * 128];           // W1^T fp16 [N][K]
__device__ __half  g_w2h[128 * 256];           // W2^T
__device__ __half  g_w3h[64 * 128];            // W3^T

__device__ __forceinline__ int load_idx(const void* ei, long long pos) {
    if (g_is64) return (int)((const long long*)ei)[pos];
    return ((const int*)ei)[pos];
}

// ---------------- fused prologue: zero counts + detect + x->fp16 + W->fp16 -
// block ranges: [0,256) init+detect, [256,8448) x2h, [8448,8576) W1,
// [8576,8704) W2, [8704,8736) W3.
__global__ void k_prologue(const int* __restrict__ ei32, const float4* __restrict__ x,
                           uint2* __restrict__ xh,
                           const float* __restrict__ W1, const float* __restrict__ W2,
                           const float* __restrict__ W3) {
    int b = blockIdx.x;
    if (b < 256) {
        int i = b * 256 + threadIdx.x;
        g_cnt[i] = 0;
        if (b == 0) {
            __shared__ int cnt;
            if (threadIdx.x == 0) cnt = 0;
            __syncthreads();
            int nz = 0;
            for (int j = threadIdx.x; j < 4096; j += 256)
                if (ei32[2 * j + 1] != 0) nz++;
            atomicAdd(&cnt, nz);
            __syncthreads();
            if (threadIdx.x == 0) g_is64 = (cnt == 0) ? 1 : 0;
        }
    } else if (b < 8448) {
        int i = (b - 256) * 256 + threadIdx.x;      // 2M float4
        float4 v = x[i];
        __half2 a = __floats2half2_rn(v.x, v.y);
        __half2 c = __floats2half2_rn(v.z, v.w);
        uint2 u;
        u.x = *(unsigned*)&a;
        u.y = *(unsigned*)&c;
        xh[i] = u;
    } else if (b < 8576) {
        int i = (b - 8448) * 256 + threadIdx.x;     // W1: N=256,K=128
        g_w1h[i] = __float2half_rn(W1[(size_t)(i % 128) * 256 + i / 128]);
    } else if (b < 8704) {
        int i = (b - 8576) * 256 + threadIdx.x;     // W2: N=128,K=256
        g_w2h[i] = __float2half_rn(W2[(size_t)(i % 256) * 128 + i / 256]);
    } else {
        int i = (b - 8704) * 256 + threadIdx.x;     // W3: N=64,K=128
        g_w3h[i] = __float2half_rn(W3[(size_t)(i % 128) * 64 + i / 128]);
    }
}

__global__ void k_count(const void* __restrict__ ei) {
    int e = blockIdx.x * blockDim.x + threadIdx.x;
    if (e < NE) {
        int d = load_idx(ei, (long long)NE + e);
        atomicAdd(&g_cnt[d], 1);
    }
}

// block-local exclusive scan of g_cnt -> g_rowptr + fused dis = rsqrt(deg+1)
__global__ void k_scan_block() {
    __shared__ int sh[1024];
    int i = blockIdx.x * 1024 + threadIdx.x;
    int v = g_cnt[i];
    g_dis[i] = rsqrtf((float)(v + 1));  // +1 self loop
    sh[threadIdx.x] = v;
    __syncthreads();
    for (int off = 1; off < 1024; off <<= 1) {
        int t = (threadIdx.x >= off) ? sh[threadIdx.x - off] : 0;
        __syncthreads();
        sh[threadIdx.x] += t;
        __syncthreads();
    }
    g_rowptr[i] = sh[threadIdx.x] - v;
    if (threadIdx.x == 1023) g_bsum[blockIdx.x] = sh[1023];
}

// add block offsets (64-partial prefix computed redundantly; proven r10/11)
__global__ void k_add_offsets() {
    __shared__ int sh[64];
    int i = blockIdx.x * 256 + threadIdx.x;
    if (threadIdx.x < 64) sh[threadIdx.x] = g_bsum[threadIdx.x];
    __syncthreads();
    int b = i >> 10;
    int off = 0;
    for (int j = 0; j < b; j++) off += sh[j];
    int r = g_rowptr[i] + off;
    g_rowptr[i] = r;
    g_cursor[i] = r;
    if (i == NN - 1) g_rowptr[NN] = r + g_cnt[i];
}

__global__ void k_fill(const void* __restrict__ ei) {
    int e = blockIdx.x * blockDim.x + threadIdx.x;
    if (e < NE) {
        int s = load_idx(ei, e);
        int d = load_idx(ei, (long long)NE + e);
        int p = atomicAdd(&g_cursor[d], 1);
        g_col[p]   = s;
        g_enorm[p] = g_dis[s] * g_dis[d];
    }
}

// ---------------- aggregation: fp16 gather, fp32 accumulate (proven) -------
template <int D, bool SM, typename OutT>
__global__ void k_agg(const uint2* __restrict__ in, const float* __restrict__ bias,
                      OutT* __restrict__ out) {
    constexpr int TPN = D / 4;
    int node = blockIdx.x * (256 / TPN) + threadIdx.x / TPN;
    int lane = threadIdx.x % TPN;
    int start = g_rowptr[node];
    int end   = g_rowptr[node + 1];
    float4 acc = make_float4(0.f, 0.f, 0.f, 0.f);
    for (int p = start; p < end; ++p) {
        int   s = g_col[p];
        float w = g_enorm[p];
        uint2 u = in[(size_t)s * TPN + lane];
        float2 f0 = __half22float2(*(__half2*)&u.x);
        float2 f1 = __half22float2(*(__half2*)&u.y);
        acc.x += w * f0.x; acc.y += w * f0.y; acc.z += w * f1.x; acc.w += w * f1.y;
    }
    {
        float ds = g_dis[node];
        float w  = ds * ds;
        uint2 u = in[(size_t)node * TPN + lane];
        float2 f0 = __half22float2(*(__half2*)&u.x);
        float2 f1 = __half22float2(*(__half2*)&u.y);
        acc.x += w * f0.x; acc.y += w * f0.y; acc.z += w * f1.x; acc.w += w * f1.y;
    }
    float v[4] = {acc.x, acc.y, acc.z, acc.w};
    if (SM) {
        int c0 = lane * 4;
        float m = 0.f;
#pragma unroll
        for (int i = 0; i < 4; i++) {
            v[i] = fmaxf(v[i] + bias[c0 + i], 0.f);
            m = fmaxf(m, v[i]);
        }
#pragma unroll
        for (int off = TPN / 2; off; off >>= 1)
            m = fmaxf(m, __shfl_xor_sync(0xffffffffu, m, off));
        float s = 0.f;
#pragma unroll
        for (int i = 0; i < 4; i++) { v[i] = expf(v[i] - m); s += v[i]; }
#pragma unroll
        for (int off = TPN / 2; off; off >>= 1)
            s += __shfl_xor_sync(0xffffffffu, s, off);
        float inv = 1.f / s;
#pragma unroll
        for (int i = 0; i < 4; i++) v[i] *= inv;
    }
    if (sizeof(OutT) == 4) {
        ((float4*)out)[(size_t)node * TPN + lane] = make_float4(v[0], v[1], v[2], v[3]);
    } else {
        __half2 h0 = __floats2half2_rn(v[0], v[1]);
        __half2 h1 = __floats2half2_rn(v[2], v[3]);
        uint2 u;
        u.x = *(unsigned*)&h0;
        u.y = *(unsigned*)&h1;
        ((uint2*)out)[(size_t)node * TPN + lane] = u;
    }
}

// ---------------- fp16 MMA helper -----------------------------------------
__device__ __forceinline__ void mma16816(float* acc, const unsigned* af,
                                         unsigned b0, unsigned b1) {
    asm volatile(
        "mma.sync.aligned.m16n8k16.row.col.f32.f16.f16.f32 "
        "{%0,%1,%2,%3}, {%4,%5,%6,%7}, {%8,%9}, {%0,%1,%2,%3};"
        : "+f"(acc[0]), "+f"(acc[1]), "+f"(acc[2]), "+f"(acc[3])
        : "r"(af[0]), "r"(af[1]), "r"(af[2]), "r"(af[3]), "r"(b0), "r"(b1));
}

// ---------------- fp16 GEMM, generic (proven round-11 body) ----------------
// C[M,N] = A[M,K] @ Wt[N,K]^T (+bias). BM=128, BN=64, BK=16, 8 warps (4Mx2N).
__global__ void k_gemm_h(const __half* __restrict__ A, const __half* __restrict__ Wt,
                         const float* __restrict__ bias, __half* __restrict__ C,
                         int K, int N) {
    __shared__ __half2 As2[128 * 12];
    __shared__ __half2 Ws2[64 * 12];
    int tid   = threadIdx.x;
    int lane  = tid & 31;
    int warp  = tid >> 5;
    int warpM = warp & 3;
    int warpN = warp >> 2;
    int qp = lane >> 2, tq = lane & 3;
    int m0 = blockIdx.x * 128, n0 = blockIdx.y * 64;

    int arow = tid >> 1, ach = (tid & 1) * 8;
    int wrow = tid >> 2, wch = (tid & 3) * 4;

    float acc[2][4][4];
#pragma unroll
    for (int a = 0; a < 2; a++)
#pragma unroll
        for (int b = 0; b < 4; b++)
#pragma unroll
            for (int c = 0; c < 4; c++) acc[a][b][c] = 0.f;

    for (int k0 = 0; k0 < K; k0 += 16) {
        {
            uint4 a = *(const uint4*)&A[(size_t)(m0 + arow) * K + k0 + ach];
            *(uint4*)&As2[arow * 12 + ach / 2] = a;
        }
        {
            uint2 w = *(const uint2*)&Wt[(size_t)(n0 + wrow) * K + k0 + wch];
            *(uint2*)&Ws2[wrow * 12 + wch / 2] = w;
        }
        __syncthreads();
        unsigned af[2][4], bf[4][2];
#pragma unroll
        for (int mt = 0; mt < 2; mt++) {
            int r = warpM * 32 + mt * 16 + qp;
            af[mt][0] = *(unsigned*)&As2[r * 12 + tq];
            af[mt][1] = *(unsigned*)&As2[(r + 8) * 12 + tq];
            af[mt][2] = *(unsigned*)&As2[r * 12 + tq + 4];
            af[mt][3] = *(unsigned*)&As2[(r + 8) * 12 + tq + 4];
        }
#pragma unroll
        for (int nt = 0; nt < 4; nt++) {
            int c = warpN * 32 + nt * 8 + qp;
            bf[nt][0] = *(unsigned*)&Ws2[c * 12 + tq];
            bf[nt][1] = *(unsigned*)&Ws2[c * 12 + tq + 4];
        }
#pragma unroll
        for (int mt = 0; mt < 2; mt++)
#pragma unroll
            for (int nt = 0; nt < 4; nt++)
                mma16816(acc[mt][nt], af[mt], bf[nt][0], bf[nt][1]);
        __syncthreads();
    }

#pragma unroll
    for (int mt = 0; mt < 2; mt++) {
#pragma unroll
        for (int nt = 0; nt < 4; nt++) {
            int col = n0 + warpN * 32 + nt * 8 + 2 * tq;
            float b0 = bias ? bias[col] : 0.f;
            float b1 = bias ? bias[col + 1] : 0.f;
            int r = m0 + warpM * 32 + mt * 16 + qp;
            __half2 h0 = __floats2half2_rn(acc[mt][nt][0] + b0, acc[mt][nt][1] + b1);
            __half2 h1 = __floats2half2_rn(acc[mt][nt][2] + b0, acc[mt][nt][3] + b1);
            *(__half2*)&C[(size_t)r * N + col] = h0;
            *(__half2*)&C[(size_t)(r + 8) * N + col] = h1;
        }
    }
}

// ---------------- GEMM1 + fused bias/ReLU/row-softmax ----------------------
// K=128, N=256, BM=64 (full 256-col row per CTA). 8 warps: 2M x 4N.
// Same smem stride-12 layout and fragment mapping as the proven kernel.
__global__ void k_gemm1_sm(const __half* __restrict__ A, const __half* __restrict__ Wt,
                           const float* __restrict__ bias, __half* __restrict__ C) {
    const int K = 128, N = 256;
    __shared__ __half2 As2[64 * 12];
    __shared__ __half2 Ws2[256 * 12];
    __shared__ float red[64 * 4];     // [row][warpN]
    int tid   = threadIdx.x;
    int lane  = tid & 31;
    int warp  = tid >> 5;
    int warpM = warp & 1;             // 2 x 32 rows
    int warpN = warp >> 1;            // 4 x 64 cols
    int qp = lane >> 2, tq = lane & 3;
    int m0 = blockIdx.x * 64;

    float acc[2][8][4];
#pragma unroll
    for (int a = 0; a < 2; a++)
#pragma unroll
        for (int b = 0; b < 8; b++)
#pragma unroll
            for (int c = 0; c < 4; c++) acc[a][b][c] = 0.f;

    for (int k0 = 0; k0 < K; k0 += 16) {
        if (tid < 128) {               // A: 64 rows x 2 chunks of 8 halves
            int row = tid >> 1, ch = (tid & 1) * 8;
            uint4 a = *(const uint4*)&A[(size_t)(m0 + row) * K + k0 + ch];
            *(uint4*)&As2[row * 12 + ch / 2] = a;
        }
#pragma unroll
        for (int i = 0; i < 2; i++) {  // W: 256 rows x 2 chunks of 8 halves
            int v = tid + i * 256;
            int row = v >> 1, ch = (v & 1) * 8;
            uint4 w = *(const uint4*)&Wt[(size_t)row * K + k0 + ch];
            *(uint4*)&Ws2[row * 12 + ch / 2] = w;
        }
        __syncthreads();
        unsigned af[2][4], bf[8][2];
#pragma unroll
        for (int mt = 0; mt < 2; mt++) {
            int r = warpM * 32 + mt * 16 + qp;
            af[mt][0] = *(unsigned*)&As2[r * 12 + tq];
            af[mt][1] = *(unsigned*)&As2[(r + 8) * 12 + tq];
            af[mt][2] = *(unsigned*)&As2[r * 12 + tq + 4];
            af[mt][3] = *(unsigned*)&As2[(r + 8) * 12 + tq + 4];
        }
#pragma unroll
        for (int nt = 0; nt < 8; nt++) {
            int c = warpN * 64 + nt * 8 + qp;
            bf[nt][0] = *(unsigned*)&Ws2[c * 12 + tq];
            bf[nt][1] = *(unsigned*)&Ws2[c * 12 + tq + 4];
        }
#pragma unroll
        for (int mt = 0; mt < 2; mt++)
#pragma unroll
            for (int nt = 0; nt < 8; nt++)
                mma16816(acc[mt][nt], af[mt], bf[nt][0], bf[nt][1]);
        __syncthreads();
    }

    // ---- epilogue: +bias -> relu -> row softmax over 256 cols -------------
    // thread owns rows (warpM*32+mt*16+qp) and +8; cols warpN*64+nt*8+2tq{,+1}
    float vmax[2][2] = {{0.f, 0.f}, {0.f, 0.f}};
#pragma unroll
    for (int mt = 0; mt < 2; mt++)
#pragma unroll
        for (int nt = 0; nt < 8; nt++) {
            int col = warpN * 64 + nt * 8 + 2 * tq;
            float b0 = bias[col], b1 = bias[col + 1];
            acc[mt][nt][0] = fmaxf(acc[mt][nt][0] + b0, 0.f);
            acc[mt][nt][1] = fmaxf(acc[mt][nt][1] + b1, 0.f);
            acc[mt][nt][2] = fmaxf(acc[mt][nt][2] + b0, 0.f);
            acc[mt][nt][3] = fmaxf(acc[mt][nt][3] + b1, 0.f);
            vmax[mt][0] = fmaxf(vmax[mt][0], fmaxf(acc[mt][nt][0], acc[mt][nt][1]));
            vmax[mt][1] = fmaxf(vmax[mt][1], fmaxf(acc[mt][nt][2], acc[mt][nt][3]));
        }
#pragma unroll
    for (int off = 1; off <= 2; off <<= 1)
#pragma unroll
        for (int mt = 0; mt < 2; mt++)
#pragma unroll
            for (int h = 0; h < 2; h++)
                vmax[mt][h] = fmaxf(vmax[mt][h], __shfl_xor_sync(0xffffffffu, vmax[mt][h], off));
    if (tq == 0) {
#pragma unroll
        for (int mt = 0; mt < 2; mt++) {
            int r = warpM * 32 + mt * 16 + qp;
            red[r * 4 + warpN] = vmax[mt][0];
            red[(r + 8) * 4 + warpN] = vmax[mt][1];
        }
    }
    __syncthreads();
    float rmax[2][2];
#pragma unroll
    for (int mt = 0; mt < 2; mt++)
#pragma unroll
        for (int h = 0; h < 2; h++) {
            int r = warpM * 32 + mt * 16 + qp + h * 8;
            rmax[mt][h] = fmaxf(fmaxf(red[r * 4], red[r * 4 + 1]),
                                fmaxf(red[r * 4 + 2], red[r * 4 + 3]));
        }
    __syncthreads();
    float vsum[2][2] = {{0.f, 0.f}, {0.f, 0.f}};
#pragma unroll
    for (int mt = 0; mt < 2; mt++)
#pragma unroll
        for (int nt = 0; nt < 8; nt++) {
            acc[mt][nt][0] = expf(acc[mt][nt][0] - rmax[mt][0]);
            acc[mt][nt][1] = expf(acc[mt][nt][1] - rmax[mt][0]);
            acc[mt][nt][2] = expf(acc[mt][nt][2] - rmax[mt][1]);
            acc[mt][nt][3] = expf(acc[mt][nt][3] - rmax[mt][1]);
            vsum[mt][0] += acc[mt][nt][0] + acc[mt][nt][1];
            vsum[mt][1] += acc[mt][nt][2] + acc[mt][nt][3];
        }
#pragma unroll
    for (int off = 1; off <= 2; off <<= 1)
#pragma unroll
        for (int mt = 0; mt < 2; mt++)
#pragma unroll
            for (int h = 0; h < 2; h++)
                vsum[mt][h] += __shfl_xor_sync(0xffffffffu, vsum[mt][h], off);
    if (tq == 0) {
#pragma unroll
        for (int mt = 0; mt < 2; mt++) {
            int r = warpM * 32 + mt * 16 + qp;
            red[r * 4 + warpN] = vsum[mt][0];
            red[(r + 8) * 4 + warpN] = vsum[mt][1];
        }
    }
    __syncthreads();
#pragma unroll
    for (int mt = 0; mt < 2; mt++) {
        float inv[2];
#pragma unroll
        for (int h = 0; h < 2; h++) {
            int r = warpM * 32 + mt * 16 + qp + h * 8;
            inv[h] = 1.f / (red[r * 4] + red[r * 4 + 1] + red[r * 4 + 2] + red[r * 4 + 3]);
        }
#pragma unroll
        for (int nt = 0; nt < 8; nt++) {
            int col = warpN * 64 + nt * 8 + 2 * tq;
            int r = m0 + warpM * 32 + mt * 16 + qp;
            __half2 h0 = __floats2half2_rn(acc[mt][nt][0] * inv[0], acc[mt][nt][1] * inv[0]);
            __half2 h1 = __floats2half2_rn(acc[mt][nt][2] * inv[1], acc[mt][nt][3] * inv[1]);
            *(__half2*)&C[(size_t)r * N + col] = h0;
            *(__half2*)&C[(size_t)(r + 8) * N + col] = h1;
        }
    }
}

// ---------------- launch ----------------------------------------------------
extern "C" void kernel_launch(void* const* d_in, const int* in_sizes, int n_in,
                              void* d_out, int out_size) {
    const float* x  = (const float*)d_in[0];
    const void*  ei = d_in[1];
    const float* W1 = (const float*)d_in[2];
    const float* b1 = (const float*)d_in[3];
    const float* W2 = (const float*)d_in[4];
    const float* b2 = (const float*)d_in[5];
    const float* W3 = (const float*)d_in[6];
    const float* b3 = (const float*)d_in[7];
    float* out = (float*)d_out;

    __half *bufAh, *bufBh, *bufH, *w1h, *w2h, *w3h;
    cudaGetSymbolAddress((void**)&bufAh, g_bufA);
    cudaGetSymbolAddress((void**)&bufBh, g_bufB);
    cudaGetSymbolAddress((void**)&bufH, g_bufH);
    cudaGetSymbolAddress((void**)&w1h, g_w1h);
    cudaGetSymbolAddress((void**)&w2h, g_w2h);
    cudaGetSymbolAddress((void**)&w3h, g_w3h);

    // ---- fused prologue + CSR build (recomputed every launch; deterministic)
    k_prologue<<<8736, 256>>>((const int*)ei, (const float4*)x, (uint2*)bufH,
                              W1, W2, W3);
    k_count<<<NE / 256, 256>>>(ei);
    k_scan_block<<<64, 1024>>>();
    k_add_offsets<<<NN / 256, 256>>>();
    k_fill<<<NE / 256, 256>>>(ei);

    // ---- layer 1: aggregate(128) -> GEMM(128->256)+b1+relu+softmax (fused)
    k_agg<128, false, __half><<<NN / 8, 256>>>((const uint2*)bufH, nullptr, bufAh);
    k_gemm1_sm<<<NN / 64, 256>>>(bufAh, w1h, b1, bufBh);

    // ---- layer 2: GEMM(256->128)->fp16 table -> aggregate+bias/relu/softmax
    k_gemm_h<<<dim3(NN / 128, 128 / 64), 256>>>(bufBh, w2h, nullptr, bufH, 256, 128);
    k_agg<128, true, __half><<<NN / 8, 256>>>((const uint2*)bufH, b2, bufAh);

    // ---- layer 3: GEMM(128->64)->fp16 table -> aggregate+bias/relu/softmax -> out
    k_gemm_h<<<dim3(NN / 128, 64 / 64), 256>>>(bufAh, w3h, nullptr, bufH, 128, 64);
    k_agg<64, true, float><<<NN / 16, 256>>>((const uint2*)bufH, b3, out);
}

// round 15
// speedup vs baseline: 1.7656x; 1.0588x over previous
#include <cuda_runtime.h>
#include <cuda_fp16.h>
#include <math.h>

#define NN 65536
#define NE 1048576

// ---------------- scratch (static device globals; no runtime alloc) --------
__device__ int     g_cnt[NN];
__device__ float   g_dis[NN];
__device__ int     g_rowptr[NN + 1];
__device__ int     g_cursor[NN];
__device__ int2    g_edge[NE];                 // {src, norm-as-int} packed
__device__ int     g_bsum[64];
__device__ int     g_is64;
__device__ float   g_bufA[(size_t)NN * 256];   // reused as __half[NN*512]
__device__ float   g_bufB[(size_t)NN * 256];
__device__ __half  g_bufH[(size_t)NN * 128];   // fp16 gather table
__device__ __half  g_w1h[256 * 128];           // W1^T fp16 [N][K]
__device__ __half  g_w2h[128 * 256];           // W2^T
__device__ __half  g_w3h[64 * 128];            // W3^T

__device__ __forceinline__ int load_idx(const void* ei, long long pos) {
    if (g_is64) return (int)((const long long*)ei)[pos];
    return ((const int*)ei)[pos];
}

// ---------------- fused prologue: zero counts + detect + x->fp16 + W->fp16 -
// block ranges: [0,256) init+detect, [256,8448) x2h, [8448,8576) W1,
// [8576,8704) W2, [8704,8736) W3.
__global__ void k_prologue(const int* __restrict__ ei32, const float4* __restrict__ x,
                           uint2* __restrict__ xh,
                           const float* __restrict__ W1, const float* __restrict__ W2,
                           const float* __restrict__ W3) {
    int b = blockIdx.x;
    if (b < 256) {
        int i = b * 256 + threadIdx.x;
        g_cnt[i] = 0;
        if (b == 0) {
            __shared__ int cnt;
            if (threadIdx.x == 0) cnt = 0;
            __syncthreads();
            int nz = 0;
            for (int j = threadIdx.x; j < 4096; j += 256)
                if (ei32[2 * j + 1] != 0) nz++;
            atomicAdd(&cnt, nz);
            __syncthreads();
            if (threadIdx.x == 0) g_is64 = (cnt == 0) ? 1 : 0;
        }
    } else if (b < 8448) {
        int i = (b - 256) * 256 + threadIdx.x;      // 2M float4
        float4 v = x[i];
        __half2 a = __floats2half2_rn(v.x, v.y);
        __half2 c = __floats2half2_rn(v.z, v.w);
        uint2 u;
        u.x = *(unsigned*)&a;
        u.y = *(unsigned*)&c;
        xh[i] = u;
    } else if (b < 8576) {
        int i = (b - 8448) * 256 + threadIdx.x;     // W1: N=256,K=128
        g_w1h[i] = __float2half_rn(W1[(size_t)(i % 128) * 256 + i / 128]);
    } else if (b < 8704) {
        int i = (b - 8576) * 256 + threadIdx.x;     // W2: N=128,K=256
        g_w2h[i] = __float2half_rn(W2[(size_t)(i % 256) * 128 + i / 256]);
    } else {
        int i = (b - 8704) * 256 + threadIdx.x;     // W3: N=64,K=128
        g_w3h[i] = __float2half_rn(W3[(size_t)(i % 128) * 64 + i / 128]);
    }
}

// ---------------- degree count: 2 edges per thread -------------------------
__global__ void k_count(const void* __restrict__ ei) {
    int e = (blockIdx.x * blockDim.x + threadIdx.x) * 2;
    if (g_is64) {
        longlong2 d = *(const longlong2*)&((const long long*)ei)[(long long)NE + e];
        atomicAdd(&g_cnt[(int)d.x], 1);
        atomicAdd(&g_cnt[(int)d.y], 1);
    } else {
        int2 d = *(const int2*)&((const int*)ei)[NE + e];
        atomicAdd(&g_cnt[d.x], 1);
        atomicAdd(&g_cnt[d.y], 1);
    }
}

// block-local exclusive scan of g_cnt -> g_rowptr + fused dis = rsqrt(deg+1)
__global__ void k_scan_block() {
    __shared__ int sh[1024];
    int i = blockIdx.x * 1024 + threadIdx.x;
    int v = g_cnt[i];
    g_dis[i] = rsqrtf((float)(v + 1));  // +1 self loop
    sh[threadIdx.x] = v;
    __syncthreads();
    for (int off = 1; off < 1024; off <<= 1) {
        int t = (threadIdx.x >= off) ? sh[threadIdx.x - off] : 0;
        __syncthreads();
        sh[threadIdx.x] += t;
        __syncthreads();
    }
    g_rowptr[i] = sh[threadIdx.x] - v;
    if (threadIdx.x == 1023) g_bsum[blockIdx.x] = sh[1023];
}

// add block offsets (64-partial prefix computed redundantly; proven r10-12)
__global__ void k_add_offsets() {
    __shared__ int sh[64];
    int i = blockIdx.x * 256 + threadIdx.x;
    if (threadIdx.x < 64) sh[threadIdx.x] = g_bsum[threadIdx.x];
    __syncthreads();
    int b = i >> 10;
    int off = 0;
    for (int j = 0; j < b; j++) off += sh[j];
    int r = g_rowptr[i] + off;
    g_rowptr[i] = r;
    g_cursor[i] = r;
    if (i == NN - 1) g_rowptr[NN] = r + g_cnt[i];
}

// ---------------- fill: 2 edges per thread, packed int2 stores -------------
__global__ void k_fill(const void* __restrict__ ei) {
    int e = (blockIdx.x * blockDim.x + threadIdx.x) * 2;
    int s0, s1, d0, d1;
    if (g_is64) {
        longlong2 sp = *(const longlong2*)&((const long long*)ei)[e];
        longlong2 dp = *(const longlong2*)&((const long long*)ei)[(long long)NE + e];
        s0 = (int)sp.x; s1 = (int)sp.y; d0 = (int)dp.x; d1 = (int)dp.y;
    } else {
        int2 sp = *(const int2*)&((const int*)ei)[e];
        int2 dp = *(const int2*)&((const int*)ei)[NE + e];
        s0 = sp.x; s1 = sp.y; d0 = dp.x; d1 = dp.y;
    }
    int p0 = atomicAdd(&g_cursor[d0], 1);
    g_edge[p0] = make_int2(s0, __float_as_int(g_dis[s0] * g_dis[d0]));
    int p1 = atomicAdd(&g_cursor[d1], 1);
    g_edge[p1] = make_int2(s1, __float_as_int(g_dis[s1] * g_dis[d1]));
}

// ---------------- aggregation: fp16 uint4 gather, fp32 accumulate ----------
// out[i] = sum_e norm_e * in[src_e] + dis[i]^2 * in[i]; optional fused
// (+bias -> relu -> row softmax) epilogue. TPN = D/8 lanes per node,
// each lane owns 8 halves (one uint4).
template <int D, bool SM, typename OutT>
__global__ void k_agg(const uint4* __restrict__ in4, const float* __restrict__ bias,
                      OutT* __restrict__ out) {
    constexpr int TPN = D / 8;                  // 16 (D=128) or 8 (D=64)
    int node = blockIdx.x * (256 / TPN) + threadIdx.x / TPN;
    int lane = threadIdx.x % TPN;
    int start = g_rowptr[node];
    int end   = g_rowptr[node + 1];
    float v[8];
#pragma unroll
    for (int i = 0; i < 8; i++) v[i] = 0.f;
    for (int p = start; p < end; ++p) {
        int2  ed = g_edge[p];
        float w  = __int_as_float(ed.y);
        uint4 u  = in4[(size_t)ed.x * TPN + lane];
        float2 f0 = __half22float2(*(__half2*)&u.x);
        float2 f1 = __half22float2(*(__half2*)&u.y);
        float2 f2 = __half22float2(*(__half2*)&u.z);
        float2 f3 = __half22float2(*(__half2*)&u.w);
        v[0] += w * f0.x; v[1] += w * f0.y; v[2] += w * f1.x; v[3] += w * f1.y;
        v[4] += w * f2.x; v[5] += w * f2.y; v[6] += w * f3.x; v[7] += w * f3.y;
    }
    {
        float ds = g_dis[node];
        float w  = ds * ds;
        uint4 u  = in4[(size_t)node * TPN + lane];
        float2 f0 = __half22float2(*(__half2*)&u.x);
        float2 f1 = __half22float2(*(__half2*)&u.y);
        float2 f2 = __half22float2(*(__half2*)&u.z);
        float2 f3 = __half22float2(*(__half2*)&u.w);
        v[0] += w * f0.x; v[1] += w * f0.y; v[2] += w * f1.x; v[3] += w * f1.y;
        v[4] += w * f2.x; v[5] += w * f2.y; v[6] += w * f3.x; v[7] += w * f3.y;
    }
    if (SM) {
        int c0 = lane * 8;
        float m = 0.f;
#pragma unroll
        for (int i = 0; i < 8; i++) {
            v[i] = fmaxf(v[i] + bias[c0 + i], 0.f);
            m = fmaxf(m, v[i]);
        }
#pragma unroll
        for (int off = TPN / 2; off; off >>= 1)
            m = fmaxf(m, __shfl_xor_sync(0xffffffffu, m, off));
        float s = 0.f;
#pragma unroll
        for (int i = 0; i < 8; i++) { v[i] = expf(v[i] - m); s += v[i]; }
#pragma unroll
        for (int off = TPN / 2; off; off >>= 1)
            s += __shfl_xor_sync(0xffffffffu, s, off);
        float inv = 1.f / s;
#pragma unroll
        for (int i = 0; i < 8; i++) v[i] *= inv;
    }
    if (sizeof(OutT) == 4) {
        float4* o = (float4*)&((float*)out)[(size_t)node * D + lane * 8];
        o[0] = make_float4(v[0], v[1], v[2], v[3]);
        o[1] = make_float4(v[4], v[5], v[6], v[7]);
    } else {
        __half2 h0 = __floats2half2_rn(v[0], v[1]);
        __half2 h1 = __floats2half2_rn(v[2], v[3]);
        __half2 h2 = __floats2half2_rn(v[4], v[5]);
        __half2 h3 = __floats2half2_rn(v[6], v[7]);
        uint4 u;
        u.x = *(unsigned*)&h0; u.y = *(unsigned*)&h1;
        u.z = *(unsigned*)&h2; u.w = *(unsigned*)&h3;
        ((uint4*)out)[(size_t)node * TPN + lane] = u;
    }
}

// ---------------- fp16 MMA helper -----------------------------------------
__device__ __forceinline__ void mma16816(float* acc, const unsigned* af,
                                         unsigned b0, unsigned b1) {
    asm volatile(
        "mma.sync.aligned.m16n8k16.row.col.f32.f16.f16.f32 "
        "{%0,%1,%2,%3}, {%4,%5,%6,%7}, {%8,%9}, {%0,%1,%2,%3};"
        : "+f"(acc[0]), "+f"(acc[1]), "+f"(acc[2]), "+f"(acc[3])
        : "r"(af[0]), "r"(af[1]), "r"(af[2]), "r"(af[3]), "r"(b0), "r"(b1));
}

// ---------------- fp16 GEMM, generic, BK=32 --------------------------------
// C[M,N] = A[M,K] @ Wt[N,K]^T (+bias). BM=128, BN=64, 8 warps (4Mx2N).
// smem rows stride 20 half2 (16 data + 4 pad): conflict-free for all four
// fragment column groups {tq, tq+4, tq+8, tq+12}.
__global__ void k_gemm_h(const __half* __restrict__ A, const __half* __restrict__ Wt,
                         const float* __restrict__ bias, __half* __restrict__ C,
                         int K, int N) {
    __shared__ __half2 As2[128 * 20];
    __shared__ __half2 Ws2[64 * 20];
    int tid   = threadIdx.x;
    int lane  = tid & 31;
    int warp  = tid >> 5;
    int warpM = warp & 3;
    int warpN = warp >> 2;
    int qp = lane >> 2, tq = lane & 3;
    int m0 = blockIdx.x * 128, n0 = blockIdx.y * 64;

    int arow = tid >> 1, ach = (tid & 1) * 16;   // A: 128 rows x 2 chunks (16 halves)
    int wrow = tid >> 2, wch = (tid & 3) * 8;    // W: 64 rows x 4 chunks (8 halves)

    float acc[2][4][4];
#pragma unroll
    for (int a = 0; a < 2; a++)
#pragma unroll
        for (int b = 0; b < 4; b++)
#pragma unroll
            for (int c = 0; c < 4; c++) acc[a][b][c] = 0.f;

    for (int k0 = 0; k0 < K; k0 += 32) {
        {
            const uint4* ag = (const uint4*)&A[(size_t)(m0 + arow) * K + k0 + ach];
            *(uint4*)&As2[arow * 20 + ach / 2] = ag[0];
            *(uint4*)&As2[arow * 20 + ach / 2 + 4] = ag[1];
            uint4 w = *(const uint4*)&Wt[(size_t)(n0 + wrow) * K + k0 + wch];
            *(uint4*)&Ws2[wrow * 20 + wch / 2] = w;
        }
        __syncthreads();
#pragma unroll
        for (int ks = 0; ks < 2; ks++) {
            int ko = ks * 8;
            unsigned af[2][4], bf[4][2];
#pragma unroll
            for (int mt = 0; mt < 2; mt++) {
                int r = warpM * 32 + mt * 16 + qp;
                af[mt][0] = *(unsigned*)&As2[r * 20 + ko + tq];
                af[mt][1] = *(unsigned*)&As2[(r + 8) * 20 + ko + tq];
                af[mt][2] = *(unsigned*)&As2[r * 20 + ko + tq + 4];
                af[mt][3] = *(unsigned*)&As2[(r + 8) * 20 + ko + tq + 4];
            }
#pragma unroll
            for (int nt = 0; nt < 4; nt++) {
                int c = warpN * 32 + nt * 8 + qp;
                bf[nt][0] = *(unsigned*)&Ws2[c * 20 + ko + tq];
                bf[nt][1] = *(unsigned*)&Ws2[c * 20 + ko + tq + 4];
            }
#pragma unroll
            for (int mt = 0; mt < 2; mt++)
#pragma unroll
                for (int nt = 0; nt < 4; nt++)
                    mma16816(acc[mt][nt], af[mt], bf[nt][0], bf[nt][1]);
        }
        __syncthreads();
    }

#pragma unroll
    for (int mt = 0; mt < 2; mt++) {
#pragma unroll
        for (int nt = 0; nt < 4; nt++) {
            int col = n0 + warpN * 32 + nt * 8 + 2 * tq;
            float b0 = bias ? bias[col] : 0.f;
            float b1 = bias ? bias[col + 1] : 0.f;
            int r = m0 + warpM * 32 + mt * 16 + qp;
            __half2 h0 = __floats2half2_rn(acc[mt][nt][0] + b0, acc[mt][nt][1] + b1);
            __half2 h1 = __floats2half2_rn(acc[mt][nt][2] + b0, acc[mt][nt][3] + b1);
            *(__half2*)&C[(size_t)r * N + col] = h0;
            *(__half2*)&C[(size_t)(r + 8) * N + col] = h1;
        }
    }
}

// ---------------- GEMM1 + fused bias/ReLU/row-softmax (proven r12) ---------
// K=128, N=256, BM=64 (full 256-col row per CTA). 8 warps: 2M x 4N.
__global__ void k_gemm1_sm(const __half* __restrict__ A, const __half* __restrict__ Wt,
                           const float* __restrict__ bias, __half* __restrict__ C) {
    const int K = 128, N = 256;
    __shared__ __half2 As2[64 * 12];
    __shared__ __half2 Ws2[256 * 12];
    __shared__ float red[64 * 4];     // [row][warpN]
    int tid   = threadIdx.x;
    int lane  = tid & 31;
    int warp  = tid >> 5;
    int warpM = warp & 1;             // 2 x 32 rows
    int warpN = warp >> 1;            // 4 x 64 cols
    int qp = lane >> 2, tq = lane & 3;
    int m0 = blockIdx.x * 64;

    float acc[2][8][4];
#pragma unroll
    for (int a = 0; a < 2; a++)
#pragma unroll
        for (int b = 0; b < 8; b++)
#pragma unroll
            for (int c = 0; c < 4; c++) acc[a][b][c] = 0.f;

    for (int k0 = 0; k0 < K; k0 += 16) {
        if (tid < 128) {
            int row = tid >> 1, ch = (tid & 1) * 8;
            uint4 a = *(const uint4*)&A[(size_t)(m0 + row) * K + k0 + ch];
            *(uint4*)&As2[row * 12 + ch / 2] = a;
        }
#pragma unroll
        for (int i = 0; i < 2; i++) {
            int v = tid + i * 256;
            int row = v >> 1, ch = (v & 1) * 8;
            uint4 w = *(const uint4*)&Wt[(size_t)row * K + k0 + ch];
            *(uint4*)&Ws2[row * 12 + ch / 2] = w;
        }
        __syncthreads();
        unsigned af[2][4], bf[8][2];
#pragma unroll
        for (int mt = 0; mt < 2; mt++) {
            int r = warpM * 32 + mt * 16 + qp;
            af[mt][0] = *(unsigned*)&As2[r * 12 + tq];
            af[mt][1] = *(unsigned*)&As2[(r + 8) * 12 + tq];
            af[mt][2] = *(unsigned*)&As2[r * 12 + tq + 4];
            af[mt][3] = *(unsigned*)&As2[(r + 8) * 12 + tq + 4];
        }
#pragma unroll
        for (int nt = 0; nt < 8; nt++) {
            int c = warpN * 64 + nt * 8 + qp;
            bf[nt][0] = *(unsigned*)&Ws2[c * 12 + tq];
            bf[nt][1] = *(unsigned*)&Ws2[c * 12 + tq + 4];
        }
#pragma unroll
        for (int mt = 0; mt < 2; mt++)
#pragma unroll
            for (int nt = 0; nt < 8; nt++)
                mma16816(acc[mt][nt], af[mt], bf[nt][0], bf[nt][1]);
        __syncthreads();
    }

    // ---- epilogue: +bias -> relu -> row softmax over 256 cols -------------
    float vmax[2][2] = {{0.f, 0.f}, {0.f, 0.f}};
#pragma unroll
    for (int mt = 0; mt < 2; mt++)
#pragma unroll
        for (int nt = 0; nt < 8; nt++) {
            int col = warpN * 64 + nt * 8 + 2 * tq;
            float b0 = bias[col], b1 = bias[col + 1];
            acc[mt][nt][0] = fmaxf(acc[mt][nt][0] + b0, 0.f);
            acc[mt][nt][1] = fmaxf(acc[mt][nt][1] + b1, 0.f);
            acc[mt][nt][2] = fmaxf(acc[mt][nt][2] + b0, 0.f);
            acc[mt][nt][3] = fmaxf(acc[mt][nt][3] + b1, 0.f);
            vmax[mt][0] = fmaxf(vmax[mt][0], fmaxf(acc[mt][nt][0], acc[mt][nt][1]));
            vmax[mt][1] = fmaxf(vmax[mt][1], fmaxf(acc[mt][nt][2], acc[mt][nt][3]));
        }
#pragma unroll
    for (int off = 1; off <= 2; off <<= 1)
#pragma unroll
        for (int mt = 0; mt < 2; mt++)
#pragma unroll
            for (int h = 0; h < 2; h++)
                vmax[mt][h] = fmaxf(vmax[mt][h], __shfl_xor_sync(0xffffffffu, vmax[mt][h], off));
    if (tq == 0) {
#pragma unroll
        for (int mt = 0; mt < 2; mt++) {
            int r = warpM * 32 + mt * 16 + qp;
            red[r * 4 + warpN] = vmax[mt][0];
            red[(r + 8) * 4 + warpN] = vmax[mt][1];
        }
    }
    __syncthreads();
    float rmax[2][2];
#pragma unroll
    for (int mt = 0; mt < 2; mt++)
#pragma unroll
        for (int h = 0; h < 2; h++) {
            int r = warpM * 32 + mt * 16 + qp + h * 8;
            rmax[mt][h] = fmaxf(fmaxf(red[r * 4], red[r * 4 + 1]),
                                fmaxf(red[r * 4 + 2], red[r * 4 + 3]));
        }
    __syncthreads();
    float vsum[2][2] = {{0.f, 0.f}, {0.f, 0.f}};
#pragma unroll
    for (int mt = 0; mt < 2; mt++)
#pragma unroll
        for (int nt = 0; nt < 8; nt++) {
            acc[mt][nt][0] = expf(acc[mt][nt][0] - rmax[mt][0]);
            acc[mt][nt][1] = expf(acc[mt][nt][1] - rmax[mt][0]);
            acc[mt][nt][2] = expf(acc[mt][nt][2] - rmax[mt][1]);
            acc[mt][nt][3] = expf(acc[mt][nt][3] - rmax[mt][1]);
            vsum[mt][0] += acc[mt][nt][0] + acc[mt][nt][1];
            vsum[mt][1] += acc[mt][nt][2] + acc[mt][nt][3];
        }
#pragma unroll
    for (int off = 1; off <= 2; off <<= 1)
#pragma unroll
        for (int mt = 0; mt < 2; mt++)
#pragma unroll
            for (int h = 0; h < 2; h++)
                vsum[mt][h] += __shfl_xor_sync(0xffffffffu, vsum[mt][h], off);
    if (tq == 0) {
#pragma unroll
        for (int mt = 0; mt < 2; mt++) {
            int r = warpM * 32 + mt * 16 + qp;
            red[r * 4 + warpN] = vsum[mt][0];
            red[(r + 8) * 4 + warpN] = vsum[mt][1];
        }
    }
    __syncthreads();
#pragma unroll
    for (int mt = 0; mt < 2; mt++) {
        float inv[2];
#pragma unroll
        for (int h = 0; h < 2; h++) {
            int r = warpM * 32 + mt * 16 + qp + h * 8;
            inv[h] = 1.f / (red[r * 4] + red[r * 4 + 1] + red[r * 4 + 2] + red[r * 4 + 3]);
        }
#pragma unroll
        for (int nt = 0; nt < 8; nt++) {
            int col = warpN * 64 + nt * 8 + 2 * tq;
            int r = m0 + warpM * 32 + mt * 16 + qp;
            __half2 h0 = __floats2half2_rn(acc[mt][nt][0] * inv[0], acc[mt][nt][1] * inv[0]);
            __half2 h1 = __floats2half2_rn(acc[mt][nt][2] * inv[1], acc[mt][nt][3] * inv[1]);
            *(__half2*)&C[(size_t)r * N + col] = h0;
            *(__half2*)&C[(size_t)(r + 8) * N + col] = h1;
        }
    }
}

// ---------------- launch ----------------------------------------------------
extern "C" void kernel_launch(void* const* d_in, const int* in_sizes, int n_in,
                              void* d_out, int out_size) {
    const float* x  = (const float*)d_in[0];
    const void*  ei = d_in[1];
    const float* W1 = (const float*)d_in[2];
    const float* b1 = (const float*)d_in[3];
    const float* W2 = (const float*)d_in[4];
    const float* b2 = (const float*)d_in[5];
    const float* W3 = (const float*)d_in[6];
    const float* b3 = (const float*)d_in[7];
    float* out = (float*)d_out;

    __half *bufAh, *bufBh, *bufH, *w1h, *w2h, *w3h;
    cudaGetSymbolAddress((void**)&bufAh, g_bufA);
    cudaGetSymbolAddress((void**)&bufBh, g_bufB);
    cudaGetSymbolAddress((void**)&bufH, g_bufH);
    cudaGetSymbolAddress((void**)&w1h, g_w1h);
    cudaGetSymbolAddress((void**)&w2h, g_w2h);
    cudaGetSymbolAddress((void**)&w3h, g_w3h);

    // ---- fused prologue + CSR build (recomputed every launch; deterministic)
    k_prologue<<<8736, 256>>>((const int*)ei, (const float4*)x, (uint2*)bufH,
                              W1, W2, W3);
    k_count<<<NE / 512, 256>>>(ei);
    k_scan_block<<<64, 1024>>>();
    k_add_offsets<<<256, 256>>>();
    k_fill<<<NE / 512, 256>>>(ei);

    // ---- layer 1: aggregate(128) -> GEMM(128->256)+b1+relu+softmax (fused)
    k_agg<128, false, __half><<<NN / 16, 256>>>((const uint4*)bufH, nullptr, bufAh);
    k_gemm1_sm<<<NN / 64, 256>>>(bufAh, w1h, b1, bufBh);

    // ---- layer 2: GEMM(256->128)->fp16 table -> aggregate+bias/relu/softmax
    k_gemm_h<<<dim3(NN / 128, 2), 256>>>(bufBh, w2h, nullptr, bufH, 256, 128);
    k_agg<128, true, __half><<<NN / 16, 256>>>((const uint4*)bufH, b2, bufAh);

    // ---- layer 3: GEMM(128->64)->fp16 table -> aggregate+bias/relu/softmax -> out
    k_gemm_h<<<dim3(NN / 128, 1), 256>>>(bufAh, w3h, nullptr, bufH, 128, 64);
    k_agg<64, true, float><<<NN / 32, 256>>>((const uint4*)bufH, b3, out);
}

// round 17
// speedup vs baseline: 1.8593x; 1.0531x over previous
#include <cuda_runtime.h>
#include <cuda_fp16.h>
#include <math.h>

#define NN 65536
#define NE 1048576

// ---------------- scratch (static device globals; no runtime alloc) --------
// INVARIANT: g_cnt is all-zero and g_flag all-zero at kernel_launch entry.
// First run: static zero-init. Later runs: k_scan re-zeroes g_cnt, k_fill
// re-zeroes g_flag, so every graph replay re-establishes the invariant.
__device__ int     g_cnt[NN];
__device__ float   g_dis[NN];
__device__ int     g_rowptr[NN + 1];
__device__ int     g_cursor[NN];
__device__ int2    g_edge[NE];                 // {src, norm-as-int} packed
__device__ int     g_bsum[64];
__device__ int     g_flag[64];
__device__ float   g_bufA[(size_t)NN * 256];   // reused as __half[NN*512]
__device__ float   g_bufB[(size_t)NN * 256];
__device__ __half  g_bufH[(size_t)NN * 128];   // fp16 gather table
__device__ __half  g_w1h[256 * 128];           // W1^T fp16 [N][K]
__device__ __half  g_w2h[128 * 256];           // W2^T
__device__ __half  g_w3h[64 * 128];            // W3^T

// int64 edge_index => every odd int32 word of the first 8 src entries is a
// zero high-half (values < 65536). int32 => real indices (P(all zero) ~ 0).
// Two L2-hot cache lines; each thread probes independently.
__device__ __forceinline__ bool detect64(const int* __restrict__ ei32) {
    unsigned nz = 0;
#pragma unroll
    for (int j = 0; j < 8; j++) nz |= (unsigned)ei32[2 * j + 1];
    return nz == 0;
}

// ---------------- fused prologue: x->fp16 + W->fp16 + degree count ---------
// block ranges: [0,8192) x2h, [8192,8320) W1, [8320,8448) W2, [8448,8480) W3,
// [8480,10528) degree count (2 edges/thread). Requires g_cnt==0 (invariant).
__global__ void k_prologue(const int* __restrict__ ei32, const float4* __restrict__ x,
                           uint2* __restrict__ xh,
                           const float* __restrict__ W1, const float* __restrict__ W2,
                           const float* __restrict__ W3) {
    int b = blockIdx.x;
    if (b < 8192) {
        int i = b * 256 + threadIdx.x;              // 2M float4
        float4 v = x[i];
        __half2 a = __floats2half2_rn(v.x, v.y);
        __half2 c = __floats2half2_rn(v.z, v.w);
        uint2 u;
        u.x = *(unsigned*)&a;
        u.y = *(unsigned*)&c;
        xh[i] = u;
    } else if (b < 8320) {
        int i = (b - 8192) * 256 + threadIdx.x;     // W1: N=256,K=128
        g_w1h[i] = __float2half_rn(W1[(size_t)(i % 128) * 256 + i / 128]);
    } else if (b < 8448) {
        int i = (b - 8320) * 256 + threadIdx.x;     // W2: N=128,K=256
        g_w2h[i] = __float2half_rn(W2[(size_t)(i % 256) * 128 + i / 256]);
    } else if (b < 8480) {
        int i = (b - 8448) * 256 + threadIdx.x;     // W3: N=64,K=128
        g_w3h[i] = __float2half_rn(W3[(size_t)(i % 128) * 64 + i / 128]);
    } else {
        int e = (b - 8480) * 512 + threadIdx.x * 2;
        if (detect64(ei32)) {
            longlong2 d = *(const longlong2*)&((const long long*)ei32)[(long long)NE + e];
            atomicAdd(&g_cnt[(int)d.x], 1);
            atomicAdd(&g_cnt[(int)d.y], 1);
        } else {
            int2 d = *(const int2*)&ei32[NE + e];
            atomicAdd(&g_cnt[d.x], 1);
            atomicAdd(&g_cnt[d.y], 1);
        }
    }
}

// ---------------- fused scan: rowptr + cursor + dis + g_cnt reset ----------
// grid 64 x 1024, single wave (148 SMs) => cross-block flag polling is
// deadlock-free. Block b: local exclusive scan, publish partial, poll
// partials of blocks < b, add offset, write rowptr/cursor, zero g_cnt.
__global__ void k_scan() {
    __shared__ int sh[1024];
    __shared__ int part[64];
    __shared__ int s_off;
    int b   = blockIdx.x;
    int tid = threadIdx.x;
    int i   = b * 1024 + tid;
    int v = g_cnt[i];
    g_cnt[i] = 0;                        // restore invariant for next replay
    g_dis[i] = rsqrtf((float)(v + 1));   // +1 self loop
    sh[tid] = v;
    __syncthreads();
    for (int off = 1; off < 1024; off <<= 1) {
        int t = (tid >= off) ? sh[tid - off] : 0;
        __syncthreads();
        sh[tid] += t;
        __syncthreads();
    }
    int local = sh[tid] - v;             // block-local exclusive
    int btot  = sh[1023];                // block total (all threads read)
    __syncthreads();
    // publish this block's partial BEFORE any polling barrier
    if (tid == 1023) {
        g_bsum[b] = btot;
        __threadfence();
        atomicExch(&g_flag[b], 1);
    }
    if (tid < 64) {
        int val = 0;
        if (tid < b) {
            while (((volatile int*)g_flag)[tid] == 0) {}
            __threadfence();
            val = g_bsum[tid];
        }
        part[tid] = val;
    }
    __syncthreads();
    if (tid == 0) {
        int s = 0;
#pragma unroll
        for (int j = 0; j < 64; j++) s += part[j];
        s_off = s;
    }
    __syncthreads();
    int r = local + s_off;
    g_rowptr[i] = r;
    g_cursor[i] = r;
    if (b == 63 && tid == 1023) g_rowptr[NN] = s_off + btot;   // == NE
}

// ---------------- fill: 2 edges per thread, packed int2 stores -------------
__global__ void k_fill(const void* __restrict__ ei) {
    if (blockIdx.x == 0 && threadIdx.x < 64) g_flag[threadIdx.x] = 0;  // reset
    int e = (blockIdx.x * blockDim.x + threadIdx.x) * 2;
    int s0, s1, d0, d1;
    if (detect64((const int*)ei)) {
        longlong2 sp = *(const longlong2*)&((const long long*)ei)[e];
        longlong2 dp = *(const longlong2*)&((const long long*)ei)[(long long)NE + e];
        s0 = (int)sp.x; s1 = (int)sp.y; d0 = (int)dp.x; d1 = (int)dp.y;
    } else {
        int2 sp = *(const int2*)&((const int*)ei)[e];
        int2 dp = *(const int2*)&((const int*)ei)[NE + e];
        s0 = sp.x; s1 = sp.y; d0 = dp.x; d1 = dp.y;
    }
    int p0 = atomicAdd(&g_cursor[d0], 1);
    g_edge[p0] = make_int2(s0, __float_as_int(g_dis[s0] * g_dis[d0]));
    int p1 = atomicAdd(&g_cursor[d1], 1);
    g_edge[p1] = make_int2(s1, __float_as_int(g_dis[s1] * g_dis[d1]));
}

// ---------------- aggregation: fp16 uint4 gather, fp32 accumulate ----------
// out[i] = sum_e norm_e * in[src_e] + dis[i]^2 * in[i]; optional fused
// (+bias -> relu -> row softmax). 2-edge unrolled for MLP.
template <int D, bool SM, typename OutT>
__global__ void k_agg(const uint4* __restrict__ in4, const float* __restrict__ bias,
                      OutT* __restrict__ out) {
    constexpr int TPN = D / 8;                  // 16 (D=128) or 8 (D=64)
    int node = blockIdx.x * (256 / TPN) + threadIdx.x / TPN;
    int lane = threadIdx.x % TPN;
    int start = g_rowptr[node];
    int end   = g_rowptr[node + 1];
    float v[8];
#pragma unroll
    for (int i = 0; i < 8; i++) v[i] = 0.f;
    int p = start;
    for (; p + 2 <= end; p += 2) {
        int2  e0 = g_edge[p];
        int2  e1 = g_edge[p + 1];
        uint4 u0 = in4[(size_t)e0.x * TPN + lane];
        uint4 u1 = in4[(size_t)e1.x * TPN + lane];
        float w0 = __int_as_float(e0.y);
        float w1 = __int_as_float(e1.y);
        float2 a0 = __half22float2(*(__half2*)&u0.x);
        float2 a1 = __half22float2(*(__half2*)&u0.y);
        float2 a2 = __half22float2(*(__half2*)&u0.z);
        float2 a3 = __half22float2(*(__half2*)&u0.w);
        v[0] += w0 * a0.x; v[1] += w0 * a0.y; v[2] += w0 * a1.x; v[3] += w0 * a1.y;
        v[4] += w0 * a2.x; v[5] += w0 * a2.y; v[6] += w0 * a3.x; v[7] += w0 * a3.y;
        float2 b0 = __half22float2(*(__half2*)&u1.x);
        float2 b1 = __half22float2(*(__half2*)&u1.y);
        float2 b2 = __half22float2(*(__half2*)&u1.z);
        float2 b3 = __half22float2(*(__half2*)&u1.w);
        v[0] += w1 * b0.x; v[1] += w1 * b0.y; v[2] += w1 * b1.x; v[3] += w1 * b1.y;
        v[4] += w1 * b2.x; v[5] += w1 * b2.y; v[6] += w1 * b3.x; v[7] += w1 * b3.y;
    }
    if (p < end) {
        int2  ed = g_edge[p];
        float w  = __int_as_float(ed.y);
        uint4 u  = in4[(size_t)ed.x * TPN + lane];
        float2 f0 = __half22float2(*(__half2*)&u.x);
        float2 f1 = __half22float2(*(__half2*)&u.y);
        float2 f2 = __half22float2(*(__half2*)&u.z);
        float2 f3 = __half22float2(*(__half2*)&u.w);
        v[0] += w * f0.x; v[1] += w * f0.y; v[2] += w * f1.x; v[3] += w * f1.y;
        v[4] += w * f2.x; v[5] += w * f2.y; v[6] += w * f3.x; v[7] += w * f3.y;
    }
    {
        float ds = g_dis[node];
        float w  = ds * ds;
        uint4 u  = in4[(size_t)node * TPN + lane];
        float2 f0 = __half22float2(*(__half2*)&u.x);
        float2 f1 = __half22float2(*(__half2*)&u.y);
        float2 f2 = __half22float2(*(__half2*)&u.z);
        float2 f3 = __half22float2(*(__half2*)&u.w);
        v[0] += w * f0.x; v[1] += w * f0.y; v[2] += w * f1.x; v[3] += w * f1.y;
        v[4] += w * f2.x; v[5] += w * f2.y; v[6] += w * f3.x; v[7] += w * f3.y;
    }
    if (SM) {
        int c0 = lane * 8;
        float m = 0.f;
#pragma unroll
        for (int i = 0; i < 8; i++) {
            v[i] = fmaxf(v[i] + bias[c0 + i], 0.f);
            m = fmaxf(m, v[i]);
        }
#pragma unroll
        for (int off = TPN / 2; off; off >>= 1)
            m = fmaxf(m, __shfl_xor_sync(0xffffffffu, m, off));
        float s = 0.f;
#pragma unroll
        for (int i = 0; i < 8; i++) { v[i] = expf(v[i] - m); s += v[i]; }
#pragma unroll
        for (int off = TPN / 2; off; off >>= 1)
            s += __shfl_xor_sync(0xffffffffu, s, off);
        float inv = 1.f / s;
#pragma unroll
        for (int i = 0; i < 8; i++) v[i] *= inv;
    }
    if (sizeof(OutT) == 4) {
        float4* o = (float4*)&((float*)out)[(size_t)node * D + lane * 8];
        o[0] = make_float4(v[0], v[1], v[2], v[3]);
        o[1] = make_float4(v[4], v[5], v[6], v[7]);
    } else {
        __half2 h0 = __floats2half2_rn(v[0], v[1]);
        __half2 h1 = __floats2half2_rn(v[2], v[3]);
        __half2 h2 = __floats2half2_rn(v[4], v[5]);
        __half2 h3 = __floats2half2_rn(v[6], v[7]);
        uint4 u;
        u.x = *(unsigned*)&h0; u.y = *(unsigned*)&h1;
        u.z = *(unsigned*)&h2; u.w = *(unsigned*)&h3;
        ((uint4*)out)[(size_t)node * TPN + lane] = u;
    }
}

// ---------------- fp16 MMA helper -----------------------------------------
__device__ __forceinline__ void mma16816(float* acc, const unsigned* af,
                                         unsigned b0, unsigned b1) {
    asm volatile(
        "mma.sync.aligned.m16n8k16.row.col.f32.f16.f16.f32 "
        "{%0,%1,%2,%3}, {%4,%5,%6,%7}, {%8,%9}, {%0,%1,%2,%3};"
        : "+f"(acc[0]), "+f"(acc[1]), "+f"(acc[2]), "+f"(acc[3])
        : "r"(af[0]), "r"(af[1]), "r"(af[2]), "r"(af[3]), "r"(b0), "r"(b1));
}

// ---------------- fp16 GEMM, generic, BK=32 (proven r12-15) ----------------
__global__ void k_gemm_h(const __half* __restrict__ A, const __half* __restrict__ Wt,
                         const float* __restrict__ bias, __half* __restrict__ C,
                         int K, int N) {
    __shared__ __half2 As2[128 * 20];
    __shared__ __half2 Ws2[64 * 20];
    int tid   = threadIdx.x;
    int lane  = tid & 31;
    int warp  = tid >> 5;
    int warpM = warp & 3;
    int warpN = warp >> 2;
    int qp = lane >> 2, tq = lane & 3;
    int m0 = blockIdx.x * 128, n0 = blockIdx.y * 64;

    int arow = tid >> 1, ach = (tid & 1) * 16;
    int wrow = tid >> 2, wch = (tid & 3) * 8;

    float acc[2][4][4];
#pragma unroll
    for (int a = 0; a < 2; a++)
#pragma unroll
        for (int b = 0; b < 4; b++)
#pragma unroll
            for (int c = 0; c < 4; c++) acc[a][b][c] = 0.f;

    for (int k0 = 0; k0 < K; k0 += 32) {
        {
            const uint4* ag = (const uint4*)&A[(size_t)(m0 + arow) * K + k0 + ach];
            *(uint4*)&As2[arow * 20 + ach / 2] = ag[0];
            *(uint4*)&As2[arow * 20 + ach / 2 + 4] = ag[1];
            uint4 w = *(const uint4*)&Wt[(size_t)(n0 + wrow) * K + k0 + wch];
            *(uint4*)&Ws2[wrow * 20 + wch / 2] = w;
        }
        __syncthreads();
#pragma unroll
        for (int ks = 0; ks < 2; ks++) {
            int ko = ks * 8;
            unsigned af[2][4], bf[4][2];
#pragma unroll
            for (int mt = 0; mt < 2; mt++) {
                int r = warpM * 32 + mt * 16 + qp;
                af[mt][0] = *(unsigned*)&As2[r * 20 + ko + tq];
                af[mt][1] = *(unsigned*)&As2[(r + 8) * 20 + ko + tq];
                af[mt][2] = *(unsigned*)&As2[r * 20 + ko + tq + 4];
                af[mt][3] = *(unsigned*)&As2[(r + 8) * 20 + ko + tq + 4];
            }
#pragma unroll
            for (int nt = 0; nt < 4; nt++) {
                int c = warpN * 32 + nt * 8 + qp;
                bf[nt][0] = *(unsigned*)&Ws2[c * 20 + ko + tq];
                bf[nt][1] = *(unsigned*)&Ws2[c * 20 + ko + tq + 4];
            }
#pragma unroll
            for (int mt = 0; mt < 2; mt++)
#pragma unroll
                for (int nt = 0; nt < 4; nt++)
                    mma16816(acc[mt][nt], af[mt], bf[nt][0], bf[nt][1]);
        }
        __syncthreads();
    }

#pragma unroll
    for (int mt = 0; mt < 2; mt++) {
#pragma unroll
        for (int nt = 0; nt < 4; nt++) {
            int col = n0 + warpN * 32 + nt * 8 + 2 * tq;
            float b0 = bias ? bias[col] : 0.f;
            float b1 = bias ? bias[col + 1] : 0.f;
            int r = m0 + warpM * 32 + mt * 16 + qp;
            __half2 h0 = __floats2half2_rn(acc[mt][nt][0] + b0, acc[mt][nt][1] + b1);
            __half2 h1 = __floats2half2_rn(acc[mt][nt][2] + b0, acc[mt][nt][3] + b1);
            *(__half2*)&C[(size_t)r * N + col] = h0;
            *(__half2*)&C[(size_t)(r + 8) * N + col] = h1;
        }
    }
}

// ---------------- GEMM1 + fused bias/ReLU/row-softmax (proven r12-15) ------
__global__ void k_gemm1_sm(const __half* __restrict__ A, const __half* __restrict__ Wt,
                           const float* __restrict__ bias, __half* __restrict__ C) {
    const int K = 128, N = 256;
    __shared__ __half2 As2[64 * 12];
    __shared__ __half2 Ws2[256 * 12];
    __shared__ float red[64 * 4];     // [row][warpN]
    int tid   = threadIdx.x;
    int lane  = tid & 31;
    int warp  = tid >> 5;
    int warpM = warp & 1;             // 2 x 32 rows
    int warpN = warp >> 1;            // 4 x 64 cols
    int qp = lane >> 2, tq = lane & 3;
    int m0 = blockIdx.x * 64;

    float acc[2][8][4];
#pragma unroll
    for (int a = 0; a < 2; a++)
#pragma unroll
        for (int b = 0; b < 8; b++)
#pragma unroll
            for (int c = 0; c < 4; c++) acc[a][b][c] = 0.f;

    for (int k0 = 0; k0 < K; k0 += 16) {
        if (tid < 128) {
            int row = tid >> 1, ch = (tid & 1) * 8;
            uint4 a = *(const uint4*)&A[(size_t)(m0 + row) * K + k0 + ch];
            *(uint4*)&As2[row * 12 + ch / 2] = a;
        }
#pragma unroll
        for (int i = 0; i < 2; i++) {
            int v = tid + i * 256;
            int row = v >> 1, ch = (v & 1) * 8;
            uint4 w = *(const uint4*)&Wt[(size_t)row * K + k0 + ch];
            *(uint4*)&Ws2[row * 12 + ch / 2] = w;
        }
        __syncthreads();
        unsigned af[2][4], bf[8][2];
#pragma unroll
        for (int mt = 0; mt < 2; mt++) {
            int r = warpM * 32 + mt * 16 + qp;
            af[mt][0] = *(unsigned*)&As2[r * 12 + tq];
            af[mt][1] = *(unsigned*)&As2[(r + 8) * 12 + tq];
            af[mt][2] = *(unsigned*)&As2[r * 12 + tq + 4];
            af[mt][3] = *(unsigned*)&As2[(r + 8) * 12 + tq + 4];
        }
#pragma unroll
        for (int nt = 0; nt < 8; nt++) {
            int c = warpN * 64 + nt * 8 + qp;
            bf[nt][0] = *(unsigned*)&Ws2[c * 12 + tq];
            bf[nt][1] = *(unsigned*)&Ws2[c * 12 + tq + 4];
        }
#pragma unroll
        for (int mt = 0; mt < 2; mt++)
#pragma unroll
            for (int nt = 0; nt < 8; nt++)
                mma16816(acc[mt][nt], af[mt], bf[nt][0], bf[nt][1]);
        __syncthreads();
    }

    // ---- epilogue: +bias -> relu -> row softmax over 256 cols -------------
    float vmax[2][2] = {{0.f, 0.f}, {0.f, 0.f}};
#pragma unroll
    for (int mt = 0; mt < 2; mt++)
#pragma unroll
        for (int nt = 0; nt < 8; nt++) {
            int col = warpN * 64 + nt * 8 + 2 * tq;
            float b0 = bias[col], b1 = bias[col + 1];
            acc[mt][nt][0] = fmaxf(acc[mt][nt][0] + b0, 0.f);
            acc[mt][nt][1] = fmaxf(acc[mt][nt][1] + b1, 0.f);
            acc[mt][nt][2] = fmaxf(acc[mt][nt][2] + b0, 0.f);
            acc[mt][nt][3] = fmaxf(acc[mt][nt][3] + b1, 0.f);
            vmax[mt][0] = fmaxf(vmax[mt][0], fmaxf(acc[mt][nt][0], acc[mt][nt][1]));
            vmax[mt][1] = fmaxf(vmax[mt][1], fmaxf(acc[mt][nt][2], acc[mt][nt][3]));
        }
#pragma unroll
    for (int off = 1; off <= 2; off <<= 1)
#pragma unroll
        for (int mt = 0; mt < 2; mt++)
#pragma unroll
            for (int h = 0; h < 2; h++)
                vmax[mt][h] = fmaxf(vmax[mt][h], __shfl_xor_sync(0xffffffffu, vmax[mt][h], off));
    if (tq == 0) {
#pragma unroll
        for (int mt = 0; mt < 2; mt++) {
            int r = warpM * 32 + mt * 16 + qp;
            red[r * 4 + warpN] = vmax[mt][0];
            red[(r + 8) * 4 + warpN] = vmax[mt][1];
        }
    }
    __syncthreads();
    float rmax[2][2];
#pragma unroll
    for (int mt = 0; mt < 2; mt++)
#pragma unroll
        for (int h = 0; h < 2; h++) {
            int r = warpM * 32 + mt * 16 + qp + h * 8;
            rmax[mt][h] = fmaxf(fmaxf(red[r * 4], red[r * 4 + 1]),
                                fmaxf(red[r * 4 + 2], red[r * 4 + 3]));
        }
    __syncthreads();
    float vsum[2][2] = {{0.f, 0.f}, {0.f, 0.f}};
#pragma unroll
    for (int mt = 0; mt < 2; mt++)
#pragma unroll
        for (int nt = 0; nt < 8; nt++) {
            acc[mt][nt][0] = expf(acc[mt][nt][0] - rmax[mt][0]);
            acc[mt][nt][1] = expf(acc[mt][nt][1] - rmax[mt][0]);
            acc[mt][nt][2] = expf(acc[mt][nt][2] - rmax[mt][1]);
            acc[mt][nt][3] = expf(acc[mt][nt][3] - rmax[mt][1]);
            vsum[mt][0] += acc[mt][nt][0] + acc[mt][nt][1];
            vsum[mt][1] += acc[mt][nt][2] + acc[mt][nt][3];
        }
#pragma unroll
    for (int off = 1; off <= 2; off <<= 1)
#pragma unroll
        for (int mt = 0; mt < 2; mt++)
#pragma unroll
            for (int h = 0; h < 2; h++)
                vsum[mt][h] += __shfl_xor_sync(0xffffffffu, vsum[mt][h], off);
    if (tq == 0) {
#pragma unroll
        for (int mt = 0; mt < 2; mt++) {
            int r = warpM * 32 + mt * 16 + qp;
            red[r * 4 + warpN] = vsum[mt][0];
            red[(r + 8) * 4 + warpN] = vsum[mt][1];
        }
    }
    __syncthreads();
#pragma unroll
    for (int mt = 0; mt < 2; mt++) {
        float inv[2];
#pragma unroll
        for (int h = 0; h < 2; h++) {
            int r = warpM * 32 + mt * 16 + qp + h * 8;
            inv[h] = 1.f / (red[r * 4] + red[r * 4 + 1] + red[r * 4 + 2] + red[r * 4 + 3]);
        }
#pragma unroll
        for (int nt = 0; nt < 8; nt++) {
            int col = warpN * 64 + nt * 8 + 2 * tq;
            int r = m0 + warpM * 32 + mt * 16 + qp;
            __half2 h0 = __floats2half2_rn(acc[mt][nt][0] * inv[0], acc[mt][nt][1] * inv[0]);
            __half2 h1 = __floats2half2_rn(acc[mt][nt][2] * inv[1], acc[mt][nt][3] * inv[1]);
            *(__half2*)&C[(size_t)r * N + col] = h0;
            *(__half2*)&C[(size_t)(r + 8) * N + col] = h1;
        }
    }
}

// ---------------- launch ----------------------------------------------------
extern "C" void kernel_launch(void* const* d_in, const int* in_sizes, int n_in,
                              void* d_out, int out_size) {
    const float* x  = (const float*)d_in[0];
    const void*  ei = d_in[1];
    const float* W1 = (const float*)d_in[2];
    const float* b1 = (const float*)d_in[3];
    const float* W2 = (const float*)d_in[4];
    const float* b2 = (const float*)d_in[5];
    const float* W3 = (const float*)d_in[6];
    const float* b3 = (const float*)d_in[7];
    float* out = (float*)d_out;

    __half *bufAh, *bufBh, *bufH, *w1h, *w2h, *w3h;
    cudaGetSymbolAddress((void**)&bufAh, g_bufA);
    cudaGetSymbolAddress((void**)&bufBh, g_bufB);
    cudaGetSymbolAddress((void**)&bufH, g_bufH);
    cudaGetSymbolAddress((void**)&w1h, g_w1h);
    cudaGetSymbolAddress((void**)&w2h, g_w2h);
    cudaGetSymbolAddress((void**)&w3h, g_w3h);

    // ---- fused prologue (conversions + degree count) + CSR build ----------
    k_prologue<<<10528, 256>>>((const int*)ei, (const float4*)x, (uint2*)bufH,
                               W1, W2, W3);
    k_scan<<<64, 1024>>>();
    k_fill<<<NE / 512, 256>>>(ei);

    // ---- layer 1: aggregate(128) -> GEMM(128->256)+b1+relu+softmax (fused)
    k_agg<128, false, __half><<<NN / 16, 256>>>((const uint4*)bufH, nullptr, bufAh);
    k_gemm1_sm<<<NN / 64, 256>>>(bufAh, w1h, b1, bufBh);

    // ---- layer 2: GEMM(256->128)->fp16 table -> aggregate+bias/relu/softmax
    k_gemm_h<<<dim3(NN / 128, 2), 256>>>(bufBh, w2h, nullptr, bufH, 256, 128);
    k_agg<128, true, __half><<<NN / 16, 256>>>((const uint4*)bufH, b2, bufAh);

    // ---- layer 3: GEMM(128->64)->fp16 table -> aggregate+bias/relu/softmax -> out
    k_gemm_h<<<dim3(NN / 128, 1), 256>>>(bufAh, w3h, nullptr, bufH, 128, 64);
    k_agg<64, true, float><<<NN / 32, 256>>>((const uint4*)bufH, b3, out);
}